// round 9
// baseline (speedup 1.0000x reference)
#include <cuda_runtime.h>
#include <cuda_bf16.h>
#include <cstdint>

#define T_TOK 4096
#define E_DIM 768
#define HN 12
#define RN 16
#define HD 64
#define ER 12288
#define K2 1536          // compact split-bf16 storage: [hi | lo]
#define NCHUNK 36        // 3 terms x 12 chunks of 64 halves

// ---------------------------------------------------------------------------
// Scratch (__device__ globals; allocation-free rule)
// ---------------------------------------------------------------------------
__device__ float g_q[T_TOK * E_DIM];
__device__ float g_attn[T_TOK * HN * RN];
__device__ float g_mid[T_TOK * E_DIM];
__device__ __align__(128) __nv_bfloat16 g_A2[(size_t)T_TOK * K2];    // value  [Vh|Vl]
__device__ __align__(128) __nv_bfloat16 g_A2x[(size_t)T_TOK * K2];   // query, then mid
__device__ __align__(128) __nv_bfloat16 g_W2[(size_t)ER * K2];       // Wv  [Wh|Wl], [N,K] K-major
__device__ __align__(128) __nv_bfloat16 g_W2q[(size_t)E_DIM * K2];   // Wq
__device__ __align__(128) __nv_bfloat16 g_W2o[(size_t)E_DIM * K2];   // Wo

// 3-term schedule over compact storage:
//   c in [0,12):  A hi, B hi     c in [12,24): A hi, B lo     c in [24,36): A lo, B hi
#define AOFF(c) (((c) < 12 ? (c) : (c) - 12) * 128L)
#define BOFF(c) (((c) < 24 ? (c) : (c) - 24) * 128L)

// ---------------------------------------------------------------------------
__device__ __forceinline__ uint32_t smem_u32(const void* p) {
    uint32_t a;
    asm("{ .reg .u64 t; cvta.to.shared.u64 t, %1; cvt.u32.u64 %0, t; }" : "=r"(a) : "l"(p));
    return a;
}

#define CP_ASYNC16(dst, src) \
    asm volatile("cp.async.cg.shared.global [%0], [%1], 16;" :: "r"(dst), "l"(src))
#define CP_COMMIT() asm volatile("cp.async.commit_group;" ::: "memory")

__device__ __forceinline__ void ldsm_x4(uint32_t& r0, uint32_t& r1, uint32_t& r2,
                                        uint32_t& r3, uint32_t addr) {
    asm volatile("ldmatrix.sync.aligned.m8n8.x4.shared.b16 {%0,%1,%2,%3}, [%4];"
                 : "=r"(r0), "=r"(r1), "=r"(r2), "=r"(r3) : "r"(addr));
}

__device__ __forceinline__ void mma_bf16(float* c, const uint32_t* a,
                                         uint32_t b0, uint32_t b1) {
    asm volatile(
        "mma.sync.aligned.m16n8k16.row.col.f32.bf16.bf16.f32 "
        "{%0,%1,%2,%3}, {%4,%5,%6,%7}, {%8,%9}, {%0,%1,%2,%3};"
        : "+f"(c[0]), "+f"(c[1]), "+f"(c[2]), "+f"(c[3])
        : "r"(a[0]), "r"(a[1]), "r"(a[2]), "r"(a[3]), "r"(b0), "r"(b1));
}

// ---------------------------------------------------------------------------
// Fuzzy membership + 16-wide softmax (proven round-7 version, unchanged)
// ---------------------------------------------------------------------------
__global__ __launch_bounds__(512) void attn_kernel(
    const float* __restrict__ rk, const float* __restrict__ rw)
{
    __shared__ float rkT[HD * RN];
    __shared__ float iwT[HD * RN];
    __shared__ float q_s[32 * 68];

    int tid = threadIdx.x;
    int t0 = blockIdx.x * 32;
    int h  = blockIdx.y;

#pragma unroll
    for (int it = 0; it < 2; it++) {
        int idx = tid + it * 512;
        int r = idx >> 6, d = idx & 63;
        float k = rk[h * (RN * HD) + idx];
        float w = rw[h * (RN * HD) + idx];
        rkT[d * RN + r] = k;
        iwT[d * RN + r] = 1.0f / (w * w);
    }
    {
        int row = tid >> 4, c = tid & 15;
        float4 v = *reinterpret_cast<const float4*>(
            &g_q[(size_t)(t0 + row) * E_DIM + h * HD + c * 4]);
        *reinterpret_cast<float4*>(&q_s[row * 68 + c * 4]) = v;
    }
    __syncthreads();

    int r  = tid & 15;
    int tl = tid >> 4;

    float s = 0.f;
#pragma unroll
    for (int d = 0; d < HD; d++) {
        float diff = q_s[tl * 68 + d] - rkT[d * RN + r];
        s = fmaf(diff * diff, iwT[d * RN + r], s);
    }
    float z = -0.5f * s * (1.0f / 64.0f);

    float m = z;
#pragma unroll
    for (int o = 8; o; o >>= 1) m = fmaxf(m, __shfl_xor_sync(0xffffffffu, m, o));
    float e = expf(z - m);
    float sum = e;
#pragma unroll
    for (int o = 8; o; o >>= 1) sum += __shfl_xor_sync(0xffffffffu, sum, o);

    g_attn[(size_t)(t0 + tl) * (HN * RN) + h * RN + r] = e / sum;
}

// ---------------------------------------------------------------------------
// Split-bf16 conversions — compact [hi | lo] layout
// ---------------------------------------------------------------------------
__global__ __launch_bounds__(256) void convert_A_kernel(
    const float* __restrict__ src, __nv_bfloat16* __restrict__ dst)
{
    int idx = blockIdx.x * 256 + threadIdx.x;
    int t = idx / E_DIM, e = idx - t * E_DIM;
    float v = src[idx];
    __nv_bfloat16 hi = __float2bfloat16(v);
    __nv_bfloat16 lo = __float2bfloat16(v - __bfloat162float(hi));
    size_t base = (size_t)t * K2 + e;
    dst[base]       = hi;
    dst[base + 768] = lo;
}

__global__ __launch_bounds__(256) void convert_W_kernel(
    const float* __restrict__ W, __nv_bfloat16* __restrict__ dst, int ldW)
{
    __shared__ float s[32][33];
    int c0 = blockIdx.x * 32, e0 = blockIdx.y * 32;
    int tx = threadIdx.x & 31, ty = threadIdx.x >> 5;
#pragma unroll
    for (int it = 0; it < 4; it++) {
        int er = ty + it * 8;
        s[er][tx] = W[(size_t)(e0 + er) * ldW + c0 + tx];
    }
    __syncthreads();
#pragma unroll
    for (int it = 0; it < 4; it++) {
        int cr = ty + it * 8;
        float v = s[tx][cr];
        __nv_bfloat16 hi = __float2bfloat16(v);
        __nv_bfloat16 lo = __float2bfloat16(v - __bfloat162float(hi));
        size_t base = (size_t)(c0 + cr) * K2 + e0 + tx;
        dst[base]       = hi;
        dst[base + 768] = lo;
    }
}

// ---------------------------------------------------------------------------
// Generic split-bf16 mma.sync GEMM (M-tile 128): C = (A2 @ W2^T + bias)*scale
// ---------------------------------------------------------------------------
#define MG_SMEM (66560 + 1024)

__global__ __launch_bounds__(256) void mma_gemm_kernel(
    const __nv_bfloat16* __restrict__ A2, const __nv_bfloat16* __restrict__ W2,
    const float* __restrict__ bias, float* __restrict__ C, float scale)
{
    extern __shared__ char smraw[];
    char* sm = (char*)(((uintptr_t)smraw + 1023) & ~(uintptr_t)1023);
    uint32_t sbase = smem_u32(sm);
    float* bias_s = reinterpret_cast<float*>(sm + 65536);

    int tid = threadIdx.x;
    int lane = tid & 31, wid = tid >> 5;
    int wm = wid & 3, wn = wid >> 2;
    int m0w = wm * 32, n0w = wn * 64;
    int bx = blockIdx.x, by = blockIdx.y;
    int m0 = by * 128;

    const char* Ab = (const char*)A2 + (size_t)m0 * (K2 * 2);
    const char* Bb = (const char*)W2 + (size_t)(bx * 128) * (K2 * 2);

    if (tid < 128) bias_s[tid] = bias[bx * 128 + tid];

    auto load_chunk = [&](int kc, int buf) {
        long ako = AOFF(kc), bko = BOFF(kc);
        uint32_t Adst = sbase + buf * 16384u;
        uint32_t Bdst = sbase + 32768u + buf * 16384u;
#pragma unroll
        for (int it = 0; it < 4; it++) {
            int f = tid + it * 256;
            int row = f >> 3, cc = f & 7;
            CP_ASYNC16(Adst + row * 128 + (((cc ^ row) & 7) << 4),
                       Ab + (long)row * (K2 * 2) + ako + cc * 16);
        }
#pragma unroll
        for (int it = 0; it < 4; it++) {
            int f = tid + it * 256;
            int row = f >> 3, cc = f & 7;
            CP_ASYNC16(Bdst + row * 128 + (((cc ^ row) & 7) << 4),
                       Bb + (long)row * (K2 * 2) + bko + cc * 16);
        }
        CP_COMMIT();
    };

    float acc[2][8][4];
#pragma unroll
    for (int i = 0; i < 2; i++)
#pragma unroll
        for (int j = 0; j < 8; j++)
#pragma unroll
            for (int e = 0; e < 4; e++) acc[i][j][e] = 0.f;

    int xr = lane & 7;
    int aRow0 = m0w + (lane & 15);
    int aU = lane >> 4;
    int bRowB = n0w + (lane & 7) + ((lane >> 4) << 3);
    int bU = (lane >> 3) & 1;

    load_chunk(0, 0);

    for (int c = 0; c < NCHUNK; c++) {
        if (c + 1 < NCHUNK) {
            load_chunk(c + 1, (c + 1) & 1);
            asm volatile("cp.async.wait_group 1;" ::: "memory");
        } else {
            asm volatile("cp.async.wait_group 0;" ::: "memory");
        }
        __syncthreads();

        uint32_t Abase = sbase + (c & 1) * 16384u;
        uint32_t Bbase = sbase + 32768u + (c & 1) * 16384u;
#pragma unroll
        for (int s = 0; s < 4; s++) {
            uint32_t a[2][4];
#pragma unroll
            for (int i = 0; i < 2; i++) {
                int u = 2 * s + aU;
                uint32_t addr = Abase + (aRow0 + 16 * i) * 128 + ((u ^ xr) << 4);
                ldsm_x4(a[i][0], a[i][1], a[i][2], a[i][3], addr);
            }
            uint32_t b[4][4];
#pragma unroll
            for (int g = 0; g < 4; g++) {
                int u = 2 * s + bU;
                uint32_t addr = Bbase + (bRowB + 16 * g) * 128 + ((u ^ xr) << 4);
                ldsm_x4(b[g][0], b[g][1], b[g][2], b[g][3], addr);
            }
#pragma unroll
            for (int i = 0; i < 2; i++)
#pragma unroll
                for (int g = 0; g < 4; g++) {
                    mma_bf16(acc[i][2 * g],     a[i], b[g][0], b[g][1]);
                    mma_bf16(acc[i][2 * g + 1], a[i], b[g][2], b[g][3]);
                }
        }
        __syncthreads();
    }

#pragma unroll
    for (int i = 0; i < 2; i++) {
        int rowL = m0 + m0w + 16 * i + (lane >> 2);
#pragma unroll
        for (int j = 0; j < 8; j++) {
            int colL = n0w + 8 * j + 2 * (lane & 3);
            int colG = bx * 128 + colL;
            float2 v0 = make_float2((acc[i][j][0] + bias_s[colL]) * scale,
                                    (acc[i][j][1] + bias_s[colL + 1]) * scale);
            float2 v1 = make_float2((acc[i][j][2] + bias_s[colL]) * scale,
                                    (acc[i][j][3] + bias_s[colL + 1]) * scale);
            *reinterpret_cast<float2*>(&C[(size_t)rowL * E_DIM + colG]) = v0;
            *reinterpret_cast<float2*>(&C[(size_t)(rowL + 8) * E_DIM + colG]) = v1;
        }
    }
}

// ---------------------------------------------------------------------------
// Fused value-GEMM + rule reduction — M-tile 256, 512 threads (8M x 2N warps).
// Per-warp mainloop identical to the proven 128-tile version.
// smem: A 2x32768 @0 | B 2x16384 @65536 | attn_s[256][17] @98304 |
//       bv_s[128] @115712 | red[256][8] @116224  -> 124416 B
// ---------------------------------------------------------------------------
#define FV_SMEM (124416 + 1024)

__global__ __launch_bounds__(512, 1) void fused_v_mma_kernel(const float* __restrict__ bv) {
    extern __shared__ char smraw[];
    char* sm = (char*)(((uintptr_t)smraw + 1023) & ~(uintptr_t)1023);
    uint32_t sbase = smem_u32(sm);
    float* attn_s = reinterpret_cast<float*>(sm + 98304);
    float* bv_s   = reinterpret_cast<float*>(sm + 115712);
    float* red    = reinterpret_cast<float*>(sm + 116224);

    int tid = threadIdx.x;
    int lane = tid & 31, wid = tid >> 5;
    int wm = wid & 7, wn = wid >> 3;          // 8 M-warps x 2 N-warps
    int m0w = wm * 32, n0w = wn * 64;
    int bx = blockIdx.x, by = blockIdx.y;
    int m0 = by * 256;
    int h = bx >> 3;
    int dbase = (bx & 7) * 8;

    const char* Ab = (const char*)g_A2 + (size_t)m0 * (K2 * 2);
    const char* Bb = (const char*)g_W2 + (size_t)(bx * 128) * (K2 * 2);

    // attn tile [256 x 16] + bias
#pragma unroll
    for (int it = 0; it < 8; it++) {
        int f = tid + it * 512;
        int row = f >> 4, r = f & 15;
        attn_s[row * 17 + r] = g_attn[(size_t)(m0 + row) * (HN * RN) + h * RN + r];
    }
    if (tid < 128) bv_s[tid] = bv[bx * 128 + tid];

    auto load_chunk = [&](int kc, int buf) {
        long ako = AOFF(kc), bko = BOFF(kc);
        uint32_t Adst = sbase + buf * 32768u;
        uint32_t Bdst = sbase + 65536u + buf * 16384u;
#pragma unroll
        for (int it = 0; it < 4; it++) {          // A: 256 rows x 128B
            int f = tid + it * 512;
            int row = f >> 3, cc = f & 7;
            CP_ASYNC16(Adst + row * 128 + (((cc ^ row) & 7) << 4),
                       Ab + (long)row * (K2 * 2) + ako + cc * 16);
        }
#pragma unroll
        for (int it = 0; it < 2; it++) {          // B: 128 rows x 128B
            int f = tid + it * 512;
            int row = f >> 3, cc = f & 7;
            CP_ASYNC16(Bdst + row * 128 + (((cc ^ row) & 7) << 4),
                       Bb + (long)row * (K2 * 2) + bko + cc * 16);
        }
        CP_COMMIT();
    };

    float acc[2][8][4];
#pragma unroll
    for (int i = 0; i < 2; i++)
#pragma unroll
        for (int j = 0; j < 8; j++)
#pragma unroll
            for (int e = 0; e < 4; e++) acc[i][j][e] = 0.f;

    int xr = lane & 7;
    int aRow0 = m0w + (lane & 15);
    int aU = lane >> 4;
    int bRowB = n0w + (lane & 7) + ((lane >> 4) << 3);
    int bU = (lane >> 3) & 1;

    load_chunk(0, 0);

    for (int c = 0; c < NCHUNK; c++) {
        if (c + 1 < NCHUNK) {
            load_chunk(c + 1, (c + 1) & 1);
            asm volatile("cp.async.wait_group 1;" ::: "memory");
        } else {
            asm volatile("cp.async.wait_group 0;" ::: "memory");
        }
        __syncthreads();

        uint32_t Abase = sbase + (c & 1) * 32768u;
        uint32_t Bbase = sbase + 65536u + (c & 1) * 16384u;
#pragma unroll
        for (int s = 0; s < 4; s++) {
            uint32_t a[2][4];
#pragma unroll
            for (int i = 0; i < 2; i++) {
                int u = 2 * s + aU;
                uint32_t addr = Abase + (aRow0 + 16 * i) * 128 + ((u ^ xr) << 4);
                ldsm_x4(a[i][0], a[i][1], a[i][2], a[i][3], addr);
            }
            uint32_t b[4][4];
#pragma unroll
            for (int g = 0; g < 4; g++) {
                int u = 2 * s + bU;
                uint32_t addr = Bbase + (bRowB + 16 * g) * 128 + ((u ^ xr) << 4);
                ldsm_x4(b[g][0], b[g][1], b[g][2], b[g][3], addr);
            }
#pragma unroll
            for (int i = 0; i < 2; i++)
#pragma unroll
                for (int g = 0; g < 4; g++) {
                    mma_bf16(acc[i][2 * g],     a[i], b[g][0], b[g][1]);
                    mma_bf16(acc[i][2 * g + 1], a[i], b[g][2], b[g][3]);
                }
        }
        __syncthreads();
    }

    // ---- Epilogue: attn-weighted rule reduction ----
    int q = lane & 3, rowg = lane >> 2;
#pragma unroll
    for (int i = 0; i < 2; i++) {
#pragma unroll
        for (int half = 0; half < 2; half++) {
            int rowL = m0w + 16 * i + rowg + 8 * half;
            float p[4] = {0.f, 0.f, 0.f, 0.f};
#pragma unroll
            for (int j = 0; j < 8; j++) {
#pragma unroll
                for (int e = 0; e < 2; e++) {
                    int clw = 8 * j + 2 * q + e;
                    int cl = n0w + clw;
                    float val = (acc[i][j][half * 2 + e] + bv_s[cl]) * 0.125f;
                    p[clw >> 4] = fmaf(attn_s[rowL * 17 + (cl & 15)], val, p[clw >> 4]);
                }
            }
#pragma unroll
            for (int d = 0; d < 4; d++) {
                p[d] += __shfl_xor_sync(0xffffffffu, p[d], 1);
                p[d] += __shfl_xor_sync(0xffffffffu, p[d], 2);
            }
            if (q == 0) {
                red[rowL * 8 + wn * 4 + 0] = p[0];
                red[rowL * 8 + wn * 4 + 1] = p[1];
                red[rowL * 8 + wn * 4 + 2] = p[2];
                red[rowL * 8 + wn * 4 + 3] = p[3];
            }
        }
    }
    __syncthreads();

    // torch scramble scatter: u = h*2048 + s; mid[b, u/12, (u%12)*64 + d]
    {
        int row = tid >> 1, part = tid & 1;       // 512 thr -> 256 rows x 2 float4
        float4 v = *reinterpret_cast<float4*>(&red[row * 8 + part * 4]);
        int t = m0 + row;
        int b = t >> 11, s = t & 2047;
        int u = h * 2048 + s;
        int jj = u / 12;
        int col0 = (u - jj * 12) * 64 + dbase + part * 4;
        *reinterpret_cast<float4*>(&g_mid[(size_t)(b * 2048 + jj) * E_DIM + col0]) = v;
    }
}

// ---------------------------------------------------------------------------
extern "C" void kernel_launch(void* const* d_in, const int* in_sizes, int n_in,
                              void* d_out, int out_size)
{
    const float* query = (const float*)d_in[0];
    const float* value = (const float*)d_in[2];
    const float* rk    = (const float*)d_in[3];
    const float* rw    = (const float*)d_in[4];
    const float* Wq    = (const float*)d_in[5];
    const float* bq    = (const float*)d_in[6];
    const float* Wv    = (const float*)d_in[7];
    const float* bv    = (const float*)d_in[8];
    const float* Wo    = (const float*)d_in[9];
    const float* bo    = (const float*)d_in[10];
    float* out = (float*)d_out;

    cudaFuncSetAttribute(fused_v_mma_kernel,
                         cudaFuncAttributeMaxDynamicSharedMemorySize, FV_SMEM);
    cudaFuncSetAttribute(mma_gemm_kernel,
                         cudaFuncAttributeMaxDynamicSharedMemorySize, MG_SMEM);

    __nv_bfloat16 *A2, *A2x, *W2, *W2q, *W2o;
    float *qbuf;
    cudaGetSymbolAddress((void**)&A2,  g_A2);
    cudaGetSymbolAddress((void**)&A2x, g_A2x);
    cudaGetSymbolAddress((void**)&W2,  g_W2);
    cudaGetSymbolAddress((void**)&W2q, g_W2q);
    cudaGetSymbolAddress((void**)&W2o, g_W2o);
    cudaGetSymbolAddress((void**)&qbuf, g_q);
    float* midbuf;
    cudaGetSymbolAddress((void**)&midbuf, g_mid);

    // q-projection (split-bf16 tensor-core GEMM) + fuzzy attn
    convert_A_kernel<<<(T_TOK * E_DIM) / 256, 256>>>(query, A2x);
    convert_W_kernel<<<dim3(E_DIM / 32, E_DIM / 32), 256>>>(Wq, W2q, E_DIM);
    mma_gemm_kernel<<<dim3(E_DIM / 128, T_TOK / 128), 256, MG_SMEM>>>(
        A2x, W2q, bq, qbuf, 0.125f);
    attn_kernel<<<dim3(T_TOK / 32, HN), 512>>>(rk, rw);

    // fused value-path GEMM + rule reduction (M-tile 256)
    convert_A_kernel<<<(T_TOK * E_DIM) / 256, 256>>>(value, A2);
    convert_W_kernel<<<dim3(ER / 32, E_DIM / 32), 256>>>(Wv, W2, ER);
    fused_v_mma_kernel<<<dim3(ER / 128, T_TOK / 256), 512, FV_SMEM>>>(bv);

    // output projection (split-bf16 tensor-core GEMM)
    convert_A_kernel<<<(T_TOK * E_DIM) / 256, 256>>>(midbuf, A2x);
    convert_W_kernel<<<dim3(E_DIM / 32, E_DIM / 32), 256>>>(Wo, W2o, E_DIM);
    mma_gemm_kernel<<<dim3(E_DIM / 128, T_TOK / 128), 256, MG_SMEM>>>(
        A2x, W2o, bo, out, 1.0f);
}

// round 10
// speedup vs baseline: 1.1230x; 1.1230x over previous
#include <cuda_runtime.h>
#include <cuda_bf16.h>
#include <cstdint>

#define T_TOK 4096
#define E_DIM 768
#define HN 12
#define RN 16
#define HD 64
#define ER 12288
#define K2 1536          // compact split-bf16 storage: [hi | lo]
#define NCHUNK 36        // 3 terms x 12 chunks of 64 halves

// ---------------------------------------------------------------------------
// Scratch (__device__ globals; allocation-free rule)
// ---------------------------------------------------------------------------
__device__ float g_q[T_TOK * E_DIM];
__device__ float g_attn[T_TOK * HN * RN];
__device__ float g_mid[T_TOK * E_DIM];
__device__ __align__(128) __nv_bfloat16 g_A2[(size_t)T_TOK * K2];    // value  [Vh|Vl]
__device__ __align__(128) __nv_bfloat16 g_A2x[(size_t)T_TOK * K2];   // query, then mid
__device__ __align__(128) __nv_bfloat16 g_W2[(size_t)ER * K2];       // Wv  [Wh|Wl], [N,K] K-major
__device__ __align__(128) __nv_bfloat16 g_W2q[(size_t)E_DIM * K2];   // Wq
__device__ __align__(128) __nv_bfloat16 g_W2o[(size_t)E_DIM * K2];   // Wo

// 3-term schedule over compact storage:
//   c in [0,12):  A hi, B hi     c in [12,24): A hi, B lo     c in [24,36): A lo, B hi
#define AOFF(c) (((c) < 12 ? (c) : (c) - 12) * 128L)
#define BOFF(c) (((c) < 24 ? (c) : (c) - 24) * 128L)

// ---------------------------------------------------------------------------
__device__ __forceinline__ uint32_t smem_u32(const void* p) {
    uint32_t a;
    asm("{ .reg .u64 t; cvta.to.shared.u64 t, %1; cvt.u32.u64 %0, t; }" : "=r"(a) : "l"(p));
    return a;
}

#define CP_ASYNC16(dst, src) \
    asm volatile("cp.async.cg.shared.global [%0], [%1], 16;" :: "r"(dst), "l"(src))
#define CP_COMMIT() asm volatile("cp.async.commit_group;" ::: "memory")

__device__ __forceinline__ void ldsm_x4(uint32_t& r0, uint32_t& r1, uint32_t& r2,
                                        uint32_t& r3, uint32_t addr) {
    asm volatile("ldmatrix.sync.aligned.m8n8.x4.shared.b16 {%0,%1,%2,%3}, [%4];"
                 : "=r"(r0), "=r"(r1), "=r"(r2), "=r"(r3) : "r"(addr));
}

__device__ __forceinline__ void mma_bf16(float* c, const uint32_t* a,
                                         uint32_t b0, uint32_t b1) {
    asm volatile(
        "mma.sync.aligned.m16n8k16.row.col.f32.bf16.bf16.f32 "
        "{%0,%1,%2,%3}, {%4,%5,%6,%7}, {%8,%9}, {%0,%1,%2,%3};"
        : "+f"(c[0]), "+f"(c[1]), "+f"(c[2]), "+f"(c[3])
        : "r"(a[0]), "r"(a[1]), "r"(a[2]), "r"(a[3]), "r"(b0), "r"(b1));
}

// ---------------------------------------------------------------------------
// Fuzzy membership + 16-wide softmax (proven round-7 version, unchanged)
// ---------------------------------------------------------------------------
__global__ __launch_bounds__(512) void attn_kernel(
    const float* __restrict__ rk, const float* __restrict__ rw)
{
    __shared__ float rkT[HD * RN];
    __shared__ float iwT[HD * RN];
    __shared__ float q_s[32 * 68];

    int tid = threadIdx.x;
    int t0 = blockIdx.x * 32;
    int h  = blockIdx.y;

#pragma unroll
    for (int it = 0; it < 2; it++) {
        int idx = tid + it * 512;
        int r = idx >> 6, d = idx & 63;
        float k = rk[h * (RN * HD) + idx];
        float w = rw[h * (RN * HD) + idx];
        rkT[d * RN + r] = k;
        iwT[d * RN + r] = 1.0f / (w * w);
    }
    {
        int row = tid >> 4, c = tid & 15;
        float4 v = *reinterpret_cast<const float4*>(
            &g_q[(size_t)(t0 + row) * E_DIM + h * HD + c * 4]);
        *reinterpret_cast<float4*>(&q_s[row * 68 + c * 4]) = v;
    }
    __syncthreads();

    int r  = tid & 15;
    int tl = tid >> 4;

    float s = 0.f;
#pragma unroll
    for (int d = 0; d < HD; d++) {
        float diff = q_s[tl * 68 + d] - rkT[d * RN + r];
        s = fmaf(diff * diff, iwT[d * RN + r], s);
    }
    float z = -0.5f * s * (1.0f / 64.0f);

    float m = z;
#pragma unroll
    for (int o = 8; o; o >>= 1) m = fmaxf(m, __shfl_xor_sync(0xffffffffu, m, o));
    float e = expf(z - m);
    float sum = e;
#pragma unroll
    for (int o = 8; o; o >>= 1) sum += __shfl_xor_sync(0xffffffffu, sum, o);

    g_attn[(size_t)(t0 + tl) * (HN * RN) + h * RN + r] = e / sum;
}

// ---------------------------------------------------------------------------
// Split-bf16 conversions — compact [hi | lo] layout
// ---------------------------------------------------------------------------
__global__ __launch_bounds__(256) void convert_A_kernel(
    const float* __restrict__ src, __nv_bfloat16* __restrict__ dst)
{
    int idx = blockIdx.x * 256 + threadIdx.x;
    int t = idx / E_DIM, e = idx - t * E_DIM;
    float v = src[idx];
    __nv_bfloat16 hi = __float2bfloat16(v);
    __nv_bfloat16 lo = __float2bfloat16(v - __bfloat162float(hi));
    size_t base = (size_t)t * K2 + e;
    dst[base]       = hi;
    dst[base + 768] = lo;
}

__global__ __launch_bounds__(256) void convert_W_kernel(
    const float* __restrict__ W, __nv_bfloat16* __restrict__ dst, int ldW)
{
    __shared__ float s[32][33];
    int c0 = blockIdx.x * 32, e0 = blockIdx.y * 32;
    int tx = threadIdx.x & 31, ty = threadIdx.x >> 5;
#pragma unroll
    for (int it = 0; it < 4; it++) {
        int er = ty + it * 8;
        s[er][tx] = W[(size_t)(e0 + er) * ldW + c0 + tx];
    }
    __syncthreads();
#pragma unroll
    for (int it = 0; it < 4; it++) {
        int cr = ty + it * 8;
        float v = s[tx][cr];
        __nv_bfloat16 hi = __float2bfloat16(v);
        __nv_bfloat16 lo = __float2bfloat16(v - __bfloat162float(hi));
        size_t base = (size_t)(c0 + cr) * K2 + e0 + tx;
        dst[base]       = hi;
        dst[base + 768] = lo;
    }
}

// ---------------------------------------------------------------------------
// Generic split-bf16 mma.sync GEMM (M-tile 128): C = (A2 @ W2^T + bias)*scale
// ---------------------------------------------------------------------------
#define MG_SMEM (66560 + 1024)

__global__ __launch_bounds__(256) void mma_gemm_kernel(
    const __nv_bfloat16* __restrict__ A2, const __nv_bfloat16* __restrict__ W2,
    const float* __restrict__ bias, float* __restrict__ C, float scale)
{
    extern __shared__ char smraw[];
    char* sm = (char*)(((uintptr_t)smraw + 1023) & ~(uintptr_t)1023);
    uint32_t sbase = smem_u32(sm);
    float* bias_s = reinterpret_cast<float*>(sm + 65536);

    int tid = threadIdx.x;
    int lane = tid & 31, wid = tid >> 5;
    int wm = wid & 3, wn = wid >> 2;
    int m0w = wm * 32, n0w = wn * 64;
    int bx = blockIdx.x, by = blockIdx.y;
    int m0 = by * 128;

    const char* Ab = (const char*)A2 + (size_t)m0 * (K2 * 2);
    const char* Bb = (const char*)W2 + (size_t)(bx * 128) * (K2 * 2);

    if (tid < 128) bias_s[tid] = bias[bx * 128 + tid];

    auto load_chunk = [&](int kc, int buf) {
        long ako = AOFF(kc), bko = BOFF(kc);
        uint32_t Adst = sbase + buf * 16384u;
        uint32_t Bdst = sbase + 32768u + buf * 16384u;
#pragma unroll
        for (int it = 0; it < 4; it++) {
            int f = tid + it * 256;
            int row = f >> 3, cc = f & 7;
            CP_ASYNC16(Adst + row * 128 + (((cc ^ row) & 7) << 4),
                       Ab + (long)row * (K2 * 2) + ako + cc * 16);
        }
#pragma unroll
        for (int it = 0; it < 4; it++) {
            int f = tid + it * 256;
            int row = f >> 3, cc = f & 7;
            CP_ASYNC16(Bdst + row * 128 + (((cc ^ row) & 7) << 4),
                       Bb + (long)row * (K2 * 2) + bko + cc * 16);
        }
        CP_COMMIT();
    };

    float acc[2][8][4];
#pragma unroll
    for (int i = 0; i < 2; i++)
#pragma unroll
        for (int j = 0; j < 8; j++)
#pragma unroll
            for (int e = 0; e < 4; e++) acc[i][j][e] = 0.f;

    int xr = lane & 7;
    int aRow0 = m0w + (lane & 15);
    int aU = lane >> 4;
    int bRowB = n0w + (lane & 7) + ((lane >> 4) << 3);
    int bU = (lane >> 3) & 1;

    load_chunk(0, 0);

    for (int c = 0; c < NCHUNK; c++) {
        if (c + 1 < NCHUNK) {
            load_chunk(c + 1, (c + 1) & 1);
            asm volatile("cp.async.wait_group 1;" ::: "memory");
        } else {
            asm volatile("cp.async.wait_group 0;" ::: "memory");
        }
        __syncthreads();

        uint32_t Abase = sbase + (c & 1) * 16384u;
        uint32_t Bbase = sbase + 32768u + (c & 1) * 16384u;
#pragma unroll
        for (int s = 0; s < 4; s++) {
            uint32_t a[2][4];
#pragma unroll
            for (int i = 0; i < 2; i++) {
                int u = 2 * s + aU;
                uint32_t addr = Abase + (aRow0 + 16 * i) * 128 + ((u ^ xr) << 4);
                ldsm_x4(a[i][0], a[i][1], a[i][2], a[i][3], addr);
            }
            uint32_t b[4][4];
#pragma unroll
            for (int g = 0; g < 4; g++) {
                int u = 2 * s + bU;
                uint32_t addr = Bbase + (bRowB + 16 * g) * 128 + ((u ^ xr) << 4);
                ldsm_x4(b[g][0], b[g][1], b[g][2], b[g][3], addr);
            }
#pragma unroll
            for (int i = 0; i < 2; i++)
#pragma unroll
                for (int g = 0; g < 4; g++) {
                    mma_bf16(acc[i][2 * g],     a[i], b[g][0], b[g][1]);
                    mma_bf16(acc[i][2 * g + 1], a[i], b[g][2], b[g][3]);
                }
        }
        __syncthreads();
    }

#pragma unroll
    for (int i = 0; i < 2; i++) {
        int rowL = m0 + m0w + 16 * i + (lane >> 2);
#pragma unroll
        for (int j = 0; j < 8; j++) {
            int colL = n0w + 8 * j + 2 * (lane & 3);
            int colG = bx * 128 + colL;
            float2 v0 = make_float2((acc[i][j][0] + bias_s[colL]) * scale,
                                    (acc[i][j][1] + bias_s[colL + 1]) * scale);
            float2 v1 = make_float2((acc[i][j][2] + bias_s[colL]) * scale,
                                    (acc[i][j][3] + bias_s[colL + 1]) * scale);
            *reinterpret_cast<float2*>(&C[(size_t)rowL * E_DIM + colG]) = v0;
            *reinterpret_cast<float2*>(&C[(size_t)(rowL + 8) * E_DIM + colG]) = v1;
        }
    }
}

// ---------------------------------------------------------------------------
// Fused value-GEMM + rule reduction — reverted to proven M-128 / 256-thread
// geometry (2 CTAs/SM); compact K2 storage retained.
// smem layout (bytes, after 1024-align):
//   0      : A tiles  2 x 16384
//   32768  : B tiles  2 x 16384
//   65536  : attn_s   float[128][17]  (8704)
//   74240  : bv_s     float[128]      (512)
//   74752  : red      float[128][8]   (4096)
// ---------------------------------------------------------------------------
#define FV_SMEM (78848 + 1024)

__global__ __launch_bounds__(256) void fused_v_mma_kernel(const float* __restrict__ bv) {
    extern __shared__ char smraw[];
    char* sm = (char*)(((uintptr_t)smraw + 1023) & ~(uintptr_t)1023);
    uint32_t sbase = smem_u32(sm);
    float* attn_s = reinterpret_cast<float*>(sm + 65536);
    float* bv_s   = reinterpret_cast<float*>(sm + 74240);
    float* red    = reinterpret_cast<float*>(sm + 74752);

    int tid = threadIdx.x;
    int lane = tid & 31, wid = tid >> 5;
    int wm = wid & 3, wn = wid >> 2;
    int m0w = wm * 32, n0w = wn * 64;
    int bx = blockIdx.x, by = blockIdx.y;
    int m0 = by * 128;
    int h = bx >> 3;
    int dbase = (bx & 7) * 8;

    const char* Ab = (const char*)g_A2 + (size_t)m0 * (K2 * 2);
    const char* Bb = (const char*)g_W2 + (size_t)(bx * 128) * (K2 * 2);

#pragma unroll
    for (int it = 0; it < 8; it++) {
        int f = tid + it * 256;
        int row = f >> 4, r = f & 15;
        attn_s[row * 17 + r] = g_attn[(size_t)(m0 + row) * (HN * RN) + h * RN + r];
    }
    if (tid < 128) bv_s[tid] = bv[bx * 128 + tid];

    auto load_chunk = [&](int kc, int buf) {
        long ako = AOFF(kc), bko = BOFF(kc);
        uint32_t Adst = sbase + buf * 16384u;
        uint32_t Bdst = sbase + 32768u + buf * 16384u;
#pragma unroll
        for (int it = 0; it < 4; it++) {
            int f = tid + it * 256;
            int row = f >> 3, cc = f & 7;
            CP_ASYNC16(Adst + row * 128 + (((cc ^ row) & 7) << 4),
                       Ab + (long)row * (K2 * 2) + ako + cc * 16);
        }
#pragma unroll
        for (int it = 0; it < 4; it++) {
            int f = tid + it * 256;
            int row = f >> 3, cc = f & 7;
            CP_ASYNC16(Bdst + row * 128 + (((cc ^ row) & 7) << 4),
                       Bb + (long)row * (K2 * 2) + bko + cc * 16);
        }
        CP_COMMIT();
    };

    float acc[2][8][4];
#pragma unroll
    for (int i = 0; i < 2; i++)
#pragma unroll
        for (int j = 0; j < 8; j++)
#pragma unroll
            for (int e = 0; e < 4; e++) acc[i][j][e] = 0.f;

    int xr = lane & 7;
    int aRow0 = m0w + (lane & 15);
    int aU = lane >> 4;
    int bRowB = n0w + (lane & 7) + ((lane >> 4) << 3);
    int bU = (lane >> 3) & 1;

    load_chunk(0, 0);

    for (int c = 0; c < NCHUNK; c++) {
        if (c + 1 < NCHUNK) {
            load_chunk(c + 1, (c + 1) & 1);
            asm volatile("cp.async.wait_group 1;" ::: "memory");
        } else {
            asm volatile("cp.async.wait_group 0;" ::: "memory");
        }
        __syncthreads();

        uint32_t Abase = sbase + (c & 1) * 16384u;
        uint32_t Bbase = sbase + 32768u + (c & 1) * 16384u;
#pragma unroll
        for (int s = 0; s < 4; s++) {
            uint32_t a[2][4];
#pragma unroll
            for (int i = 0; i < 2; i++) {
                int u = 2 * s + aU;
                uint32_t addr = Abase + (aRow0 + 16 * i) * 128 + ((u ^ xr) << 4);
                ldsm_x4(a[i][0], a[i][1], a[i][2], a[i][3], addr);
            }
            uint32_t b[4][4];
#pragma unroll
            for (int g = 0; g < 4; g++) {
                int u = 2 * s + bU;
                uint32_t addr = Bbase + (bRowB + 16 * g) * 128 + ((u ^ xr) << 4);
                ldsm_x4(b[g][0], b[g][1], b[g][2], b[g][3], addr);
            }
#pragma unroll
            for (int i = 0; i < 2; i++)
#pragma unroll
                for (int g = 0; g < 4; g++) {
                    mma_bf16(acc[i][2 * g],     a[i], b[g][0], b[g][1]);
                    mma_bf16(acc[i][2 * g + 1], a[i], b[g][2], b[g][3]);
                }
        }
        __syncthreads();
    }

    // ---- Epilogue: attn-weighted rule reduction ----
    int q = lane & 3, rowg = lane >> 2;
#pragma unroll
    for (int i = 0; i < 2; i++) {
#pragma unroll
        for (int half = 0; half < 2; half++) {
            int rowL = m0w + 16 * i + rowg + 8 * half;
            float p[4] = {0.f, 0.f, 0.f, 0.f};
#pragma unroll
            for (int j = 0; j < 8; j++) {
#pragma unroll
                for (int e = 0; e < 2; e++) {
                    int clw = 8 * j + 2 * q + e;
                    int cl = n0w + clw;
                    float val = (acc[i][j][half * 2 + e] + bv_s[cl]) * 0.125f;
                    p[clw >> 4] = fmaf(attn_s[rowL * 17 + (cl & 15)], val, p[clw >> 4]);
                }
            }
#pragma unroll
            for (int d = 0; d < 4; d++) {
                p[d] += __shfl_xor_sync(0xffffffffu, p[d], 1);
                p[d] += __shfl_xor_sync(0xffffffffu, p[d], 2);
            }
            if (q == 0) {
                red[rowL * 8 + wn * 4 + 0] = p[0];
                red[rowL * 8 + wn * 4 + 1] = p[1];
                red[rowL * 8 + wn * 4 + 2] = p[2];
                red[rowL * 8 + wn * 4 + 3] = p[3];
            }
        }
    }
    __syncthreads();

    // torch scramble scatter: u = h*2048 + s; mid[b, u/12, (u%12)*64 + d]
    {
        int row = tid >> 1, part = tid & 1;
        float4 v = *reinterpret_cast<float4*>(&red[row * 8 + part * 4]);
        int t = m0 + row;
        int b = t >> 11, s = t & 2047;
        int u = h * 2048 + s;
        int jj = u / 12;
        int col0 = (u - jj * 12) * 64 + dbase + part * 4;
        *reinterpret_cast<float4*>(&g_mid[(size_t)(b * 2048 + jj) * E_DIM + col0]) = v;
    }
}

// ---------------------------------------------------------------------------
extern "C" void kernel_launch(void* const* d_in, const int* in_sizes, int n_in,
                              void* d_out, int out_size)
{
    const float* query = (const float*)d_in[0];
    const float* value = (const float*)d_in[2];
    const float* rk    = (const float*)d_in[3];
    const float* rw    = (const float*)d_in[4];
    const float* Wq    = (const float*)d_in[5];
    const float* bq    = (const float*)d_in[6];
    const float* Wv    = (const float*)d_in[7];
    const float* bv    = (const float*)d_in[8];
    const float* Wo    = (const float*)d_in[9];
    const float* bo    = (const float*)d_in[10];
    float* out = (float*)d_out;

    cudaFuncSetAttribute(fused_v_mma_kernel,
                         cudaFuncAttributeMaxDynamicSharedMemorySize, FV_SMEM);
    cudaFuncSetAttribute(mma_gemm_kernel,
                         cudaFuncAttributeMaxDynamicSharedMemorySize, MG_SMEM);

    __nv_bfloat16 *A2, *A2x, *W2, *W2q, *W2o;
    float *qbuf;
    cudaGetSymbolAddress((void**)&A2,  g_A2);
    cudaGetSymbolAddress((void**)&A2x, g_A2x);
    cudaGetSymbolAddress((void**)&W2,  g_W2);
    cudaGetSymbolAddress((void**)&W2q, g_W2q);
    cudaGetSymbolAddress((void**)&W2o, g_W2o);
    cudaGetSymbolAddress((void**)&qbuf, g_q);
    float* midbuf;
    cudaGetSymbolAddress((void**)&midbuf, g_mid);

    // q-projection (split-bf16 tensor-core GEMM) + fuzzy attn
    convert_A_kernel<<<(T_TOK * E_DIM) / 256, 256>>>(query, A2x);
    convert_W_kernel<<<dim3(E_DIM / 32, E_DIM / 32), 256>>>(Wq, W2q, E_DIM);
    mma_gemm_kernel<<<dim3(E_DIM / 128, T_TOK / 128), 256, MG_SMEM>>>(
        A2x, W2q, bq, qbuf, 0.125f);
    attn_kernel<<<dim3(T_TOK / 32, HN), 512>>>(rk, rw);

    // fused value-path GEMM + rule reduction (M-tile 128, 2 CTAs/SM)
    convert_A_kernel<<<(T_TOK * E_DIM) / 256, 256>>>(value, A2);
    convert_W_kernel<<<dim3(ER / 32, E_DIM / 32), 256>>>(Wv, W2, ER);
    fused_v_mma_kernel<<<dim3(ER / 128, T_TOK / 128), 256, FV_SMEM>>>(bv);

    // output projection (split-bf16 tensor-core GEMM)
    convert_A_kernel<<<(T_TOK * E_DIM) / 256, 256>>>(midbuf, A2x);
    convert_W_kernel<<<dim3(E_DIM / 32, E_DIM / 32), 256>>>(Wo, W2o, E_DIM);
    mma_gemm_kernel<<<dim3(E_DIM / 128, T_TOK / 128), 256, MG_SMEM>>>(
        A2x, W2o, bo, out, 1.0f);
}

// round 11
// speedup vs baseline: 1.1230x; 1.0000x over previous
#include <cuda_runtime.h>
#include <cuda_bf16.h>
#include <cstdint>

#define T_TOK 4096
#define E_DIM 768
#define HN 12
#define RN 16
#define HD 64
#define ER 12288
#define K2 1536          // compact split-bf16 storage: [hi | lo]
#define NCHUNK 36        // 3 terms x 12 chunks of 64 halves

// ---------------------------------------------------------------------------
// Scratch (__device__ globals; allocation-free rule)
// ---------------------------------------------------------------------------
__device__ float g_q[T_TOK * E_DIM];
__device__ float g_attn[T_TOK * HN * RN];
__device__ __align__(128) __nv_bfloat16 g_A2[(size_t)T_TOK * K2];    // value  [Vh|Vl]
__device__ __align__(128) __nv_bfloat16 g_A2x[(size_t)T_TOK * K2];   // query, then mid (split, scrambled)
__device__ __align__(128) __nv_bfloat16 g_W2[(size_t)ER * K2];       // Wv  [Wh|Wl], [N,K] K-major
__device__ __align__(128) __nv_bfloat16 g_W2q[(size_t)E_DIM * K2];   // Wq
__device__ __align__(128) __nv_bfloat16 g_W2o[(size_t)E_DIM * K2];   // Wo

// 3-term schedule over compact storage:
//   c in [0,12):  A hi, B hi     c in [12,24): A hi, B lo     c in [24,36): A lo, B hi
#define AOFF(c) (((c) < 12 ? (c) : (c) - 12) * 128L)
#define BOFF(c) (((c) < 24 ? (c) : (c) - 24) * 128L)

// ---------------------------------------------------------------------------
__device__ __forceinline__ uint32_t smem_u32(const void* p) {
    uint32_t a;
    asm("{ .reg .u64 t; cvta.to.shared.u64 t, %1; cvt.u32.u64 %0, t; }" : "=r"(a) : "l"(p));
    return a;
}

#define CP_ASYNC16(dst, src) \
    asm volatile("cp.async.cg.shared.global [%0], [%1], 16;" :: "r"(dst), "l"(src))
#define CP_COMMIT() asm volatile("cp.async.commit_group;" ::: "memory")

__device__ __forceinline__ void ldsm_x4(uint32_t& r0, uint32_t& r1, uint32_t& r2,
                                        uint32_t& r3, uint32_t addr) {
    asm volatile("ldmatrix.sync.aligned.m8n8.x4.shared.b16 {%0,%1,%2,%3}, [%4];"
                 : "=r"(r0), "=r"(r1), "=r"(r2), "=r"(r3) : "r"(addr));
}

__device__ __forceinline__ void mma_bf16(float* c, const uint32_t* a,
                                         uint32_t b0, uint32_t b1) {
    asm volatile(
        "mma.sync.aligned.m16n8k16.row.col.f32.bf16.bf16.f32 "
        "{%0,%1,%2,%3}, {%4,%5,%6,%7}, {%8,%9}, {%0,%1,%2,%3};"
        : "+f"(c[0]), "+f"(c[1]), "+f"(c[2]), "+f"(c[3])
        : "r"(a[0]), "r"(a[1]), "r"(a[2]), "r"(a[3]), "r"(b0), "r"(b1));
}

// ---------------------------------------------------------------------------
// Fuzzy membership + 16-wide softmax (proven round-7 version, unchanged)
// ---------------------------------------------------------------------------
__global__ __launch_bounds__(512) void attn_kernel(
    const float* __restrict__ rk, const float* __restrict__ rw)
{
    __shared__ float rkT[HD * RN];
    __shared__ float iwT[HD * RN];
    __shared__ float q_s[32 * 68];

    int tid = threadIdx.x;
    int t0 = blockIdx.x * 32;
    int h  = blockIdx.y;

#pragma unroll
    for (int it = 0; it < 2; it++) {
        int idx = tid + it * 512;
        int r = idx >> 6, d = idx & 63;
        float k = rk[h * (RN * HD) + idx];
        float w = rw[h * (RN * HD) + idx];
        rkT[d * RN + r] = k;
        iwT[d * RN + r] = 1.0f / (w * w);
    }
    {
        int row = tid >> 4, c = tid & 15;
        float4 v = *reinterpret_cast<const float4*>(
            &g_q[(size_t)(t0 + row) * E_DIM + h * HD + c * 4]);
        *reinterpret_cast<float4*>(&q_s[row * 68 + c * 4]) = v;
    }
    __syncthreads();

    int r  = tid & 15;
    int tl = tid >> 4;

    float s = 0.f;
#pragma unroll
    for (int d = 0; d < HD; d++) {
        float diff = q_s[tl * 68 + d] - rkT[d * RN + r];
        s = fmaf(diff * diff, iwT[d * RN + r], s);
    }
    float z = -0.5f * s * (1.0f / 64.0f);

    float m = z;
#pragma unroll
    for (int o = 8; o; o >>= 1) m = fmaxf(m, __shfl_xor_sync(0xffffffffu, m, o));
    float e = expf(z - m);
    float sum = e;
#pragma unroll
    for (int o = 8; o; o >>= 1) sum += __shfl_xor_sync(0xffffffffu, sum, o);

    g_attn[(size_t)(t0 + tl) * (HN * RN) + h * RN + r] = e / sum;
}

// ---------------------------------------------------------------------------
// Split-bf16 conversions — compact [hi | lo] layout
// ---------------------------------------------------------------------------
__global__ __launch_bounds__(256) void convert_A_kernel(
    const float* __restrict__ src, __nv_bfloat16* __restrict__ dst)
{
    int idx = blockIdx.x * 256 + threadIdx.x;
    int t = idx / E_DIM, e = idx - t * E_DIM;
    float v = src[idx];
    __nv_bfloat16 hi = __float2bfloat16(v);
    __nv_bfloat16 lo = __float2bfloat16(v - __bfloat162float(hi));
    size_t base = (size_t)t * K2 + e;
    dst[base]       = hi;
    dst[base + 768] = lo;
}

__global__ __launch_bounds__(256) void convert_W_kernel(
    const float* __restrict__ W, __nv_bfloat16* __restrict__ dst, int ldW)
{
    __shared__ float s[32][33];
    int c0 = blockIdx.x * 32, e0 = blockIdx.y * 32;
    int tx = threadIdx.x & 31, ty = threadIdx.x >> 5;
#pragma unroll
    for (int it = 0; it < 4; it++) {
        int er = ty + it * 8;
        s[er][tx] = W[(size_t)(e0 + er) * ldW + c0 + tx];
    }
    __syncthreads();
#pragma unroll
    for (int it = 0; it < 4; it++) {
        int cr = ty + it * 8;
        float v = s[tx][cr];
        __nv_bfloat16 hi = __float2bfloat16(v);
        __nv_bfloat16 lo = __float2bfloat16(v - __bfloat162float(hi));
        size_t base = (size_t)(c0 + cr) * K2 + e0 + tx;
        dst[base]       = hi;
        dst[base + 768] = lo;
    }
}

// ---------------------------------------------------------------------------
// Generic split-bf16 mma.sync GEMM (M-tile 128): C = (A2 @ W2^T + bias)*scale
// ---------------------------------------------------------------------------
#define MG_SMEM (66560 + 1024)

__global__ __launch_bounds__(256) void mma_gemm_kernel(
    const __nv_bfloat16* __restrict__ A2, const __nv_bfloat16* __restrict__ W2,
    const float* __restrict__ bias, float* __restrict__ C, float scale)
{
    extern __shared__ char smraw[];
    char* sm = (char*)(((uintptr_t)smraw + 1023) & ~(uintptr_t)1023);
    uint32_t sbase = smem_u32(sm);
    float* bias_s = reinterpret_cast<float*>(sm + 65536);

    int tid = threadIdx.x;
    int lane = tid & 31, wid = tid >> 5;
    int wm = wid & 3, wn = wid >> 2;
    int m0w = wm * 32, n0w = wn * 64;
    int bx = blockIdx.x, by = blockIdx.y;
    int m0 = by * 128;

    const char* Ab = (const char*)A2 + (size_t)m0 * (K2 * 2);
    const char* Bb = (const char*)W2 + (size_t)(bx * 128) * (K2 * 2);

    if (tid < 128) bias_s[tid] = bias[bx * 128 + tid];

    auto load_chunk = [&](int kc, int buf) {
        long ako = AOFF(kc), bko = BOFF(kc);
        uint32_t Adst = sbase + buf * 16384u;
        uint32_t Bdst = sbase + 32768u + buf * 16384u;
#pragma unroll
        for (int it = 0; it < 4; it++) {
            int f = tid + it * 256;
            int row = f >> 3, cc = f & 7;
            CP_ASYNC16(Adst + row * 128 + (((cc ^ row) & 7) << 4),
                       Ab + (long)row * (K2 * 2) + ako + cc * 16);
        }
#pragma unroll
        for (int it = 0; it < 4; it++) {
            int f = tid + it * 256;
            int row = f >> 3, cc = f & 7;
            CP_ASYNC16(Bdst + row * 128 + (((cc ^ row) & 7) << 4),
                       Bb + (long)row * (K2 * 2) + bko + cc * 16);
        }
        CP_COMMIT();
    };

    float acc[2][8][4];
#pragma unroll
    for (int i = 0; i < 2; i++)
#pragma unroll
        for (int j = 0; j < 8; j++)
#pragma unroll
            for (int e = 0; e < 4; e++) acc[i][j][e] = 0.f;

    int xr = lane & 7;
    int aRow0 = m0w + (lane & 15);
    int aU = lane >> 4;
    int bRowB = n0w + (lane & 7) + ((lane >> 4) << 3);
    int bU = (lane >> 3) & 1;

    load_chunk(0, 0);

    for (int c = 0; c < NCHUNK; c++) {
        if (c + 1 < NCHUNK) {
            load_chunk(c + 1, (c + 1) & 1);
            asm volatile("cp.async.wait_group 1;" ::: "memory");
        } else {
            asm volatile("cp.async.wait_group 0;" ::: "memory");
        }
        __syncthreads();

        uint32_t Abase = sbase + (c & 1) * 16384u;
        uint32_t Bbase = sbase + 32768u + (c & 1) * 16384u;
#pragma unroll
        for (int s = 0; s < 4; s++) {
            uint32_t a[2][4];
#pragma unroll
            for (int i = 0; i < 2; i++) {
                int u = 2 * s + aU;
                uint32_t addr = Abase + (aRow0 + 16 * i) * 128 + ((u ^ xr) << 4);
                ldsm_x4(a[i][0], a[i][1], a[i][2], a[i][3], addr);
            }
            uint32_t b[4][4];
#pragma unroll
            for (int g = 0; g < 4; g++) {
                int u = 2 * s + bU;
                uint32_t addr = Bbase + (bRowB + 16 * g) * 128 + ((u ^ xr) << 4);
                ldsm_x4(b[g][0], b[g][1], b[g][2], b[g][3], addr);
            }
#pragma unroll
            for (int i = 0; i < 2; i++)
#pragma unroll
                for (int g = 0; g < 4; g++) {
                    mma_bf16(acc[i][2 * g],     a[i], b[g][0], b[g][1]);
                    mma_bf16(acc[i][2 * g + 1], a[i], b[g][2], b[g][3]);
                }
        }
        __syncthreads();
    }

#pragma unroll
    for (int i = 0; i < 2; i++) {
        int rowL = m0 + m0w + 16 * i + (lane >> 2);
#pragma unroll
        for (int j = 0; j < 8; j++) {
            int colL = n0w + 8 * j + 2 * (lane & 3);
            int colG = bx * 128 + colL;
            float2 v0 = make_float2((acc[i][j][0] + bias_s[colL]) * scale,
                                    (acc[i][j][1] + bias_s[colL + 1]) * scale);
            float2 v1 = make_float2((acc[i][j][2] + bias_s[colL]) * scale,
                                    (acc[i][j][3] + bias_s[colL + 1]) * scale);
            *reinterpret_cast<float2*>(&C[(size_t)rowL * E_DIM + colG]) = v0;
            *reinterpret_cast<float2*>(&C[(size_t)(rowL + 8) * E_DIM + colG]) = v1;
        }
    }
}

// ---------------------------------------------------------------------------
// Fused value-GEMM + rule reduction — M-128 / 256-thread (2 CTAs/SM),
// 3-stage cp.async pipeline; epilogue writes split-bf16 mid directly to g_A2x.
// smem layout (bytes, after 1024-align):
//   0      : A tiles  3 x 16384 (49152)
//   49152  : B tiles  3 x 16384 (49152)
//   98304  : attn_s   float[128][17]  (8704)
//   107008 : bv_s     float[128]      (512)
//   107520 : red      float[128][8]   (4096)  -> 111616
// ---------------------------------------------------------------------------
#define FV_SMEM (111616 + 1024)

__global__ __launch_bounds__(256) void fused_v_mma_kernel(const float* __restrict__ bv) {
    extern __shared__ char smraw[];
    char* sm = (char*)(((uintptr_t)smraw + 1023) & ~(uintptr_t)1023);
    uint32_t sbase = smem_u32(sm);
    float* attn_s = reinterpret_cast<float*>(sm + 98304);
    float* bv_s   = reinterpret_cast<float*>(sm + 107008);
    float* red    = reinterpret_cast<float*>(sm + 107520);

    int tid = threadIdx.x;
    int lane = tid & 31, wid = tid >> 5;
    int wm = wid & 3, wn = wid >> 2;
    int m0w = wm * 32, n0w = wn * 64;
    int bx = blockIdx.x, by = blockIdx.y;
    int m0 = by * 128;
    int h = bx >> 3;
    int dbase = (bx & 7) * 8;

    const char* Ab = (const char*)g_A2 + (size_t)m0 * (K2 * 2);
    const char* Bb = (const char*)g_W2 + (size_t)(bx * 128) * (K2 * 2);

#pragma unroll
    for (int it = 0; it < 8; it++) {
        int f = tid + it * 256;
        int row = f >> 4, r = f & 15;
        attn_s[row * 17 + r] = g_attn[(size_t)(m0 + row) * (HN * RN) + h * RN + r];
    }
    if (tid < 128) bv_s[tid] = bv[bx * 128 + tid];

    auto load_chunk = [&](int kc, int buf) {
        long ako = AOFF(kc), bko = BOFF(kc);
        uint32_t Adst = sbase + buf * 16384u;
        uint32_t Bdst = sbase + 49152u + buf * 16384u;
#pragma unroll
        for (int it = 0; it < 4; it++) {
            int f = tid + it * 256;
            int row = f >> 3, cc = f & 7;
            CP_ASYNC16(Adst + row * 128 + (((cc ^ row) & 7) << 4),
                       Ab + (long)row * (K2 * 2) + ako + cc * 16);
        }
#pragma unroll
        for (int it = 0; it < 4; it++) {
            int f = tid + it * 256;
            int row = f >> 3, cc = f & 7;
            CP_ASYNC16(Bdst + row * 128 + (((cc ^ row) & 7) << 4),
                       Bb + (long)row * (K2 * 2) + bko + cc * 16);
        }
        CP_COMMIT();
    };

    float acc[2][8][4];
#pragma unroll
    for (int i = 0; i < 2; i++)
#pragma unroll
        for (int j = 0; j < 8; j++)
#pragma unroll
            for (int e = 0; e < 4; e++) acc[i][j][e] = 0.f;

    int xr = lane & 7;
    int aRow0 = m0w + (lane & 15);
    int aU = lane >> 4;
    int bRowB = n0w + (lane & 7) + ((lane >> 4) << 3);
    int bU = (lane >> 3) & 1;

    // 3-stage pipeline: keep two chunks in flight
    load_chunk(0, 0);
    load_chunk(1, 1);

    for (int c = 0; c < NCHUNK; c++) {
        if (c + 2 < NCHUNK) {
            load_chunk(c + 2, (c + 2) % 3);
            asm volatile("cp.async.wait_group 2;" ::: "memory");
        } else if (c + 1 < NCHUNK) {
            asm volatile("cp.async.wait_group 1;" ::: "memory");
        } else {
            asm volatile("cp.async.wait_group 0;" ::: "memory");
        }
        __syncthreads();

        uint32_t Abase = sbase + (c % 3) * 16384u;
        uint32_t Bbase = sbase + 49152u + (c % 3) * 16384u;
#pragma unroll
        for (int s = 0; s < 4; s++) {
            uint32_t a[2][4];
#pragma unroll
            for (int i = 0; i < 2; i++) {
                int u = 2 * s + aU;
                uint32_t addr = Abase + (aRow0 + 16 * i) * 128 + ((u ^ xr) << 4);
                ldsm_x4(a[i][0], a[i][1], a[i][2], a[i][3], addr);
            }
            uint32_t b[4][4];
#pragma unroll
            for (int g = 0; g < 4; g++) {
                int u = 2 * s + bU;
                uint32_t addr = Bbase + (bRowB + 16 * g) * 128 + ((u ^ xr) << 4);
                ldsm_x4(b[g][0], b[g][1], b[g][2], b[g][3], addr);
            }
#pragma unroll
            for (int i = 0; i < 2; i++)
#pragma unroll
                for (int g = 0; g < 4; g++) {
                    mma_bf16(acc[i][2 * g],     a[i], b[g][0], b[g][1]);
                    mma_bf16(acc[i][2 * g + 1], a[i], b[g][2], b[g][3]);
                }
        }
        __syncthreads();
    }

    // ---- Epilogue: attn-weighted rule reduction ----
    int q = lane & 3, rowg = lane >> 2;
#pragma unroll
    for (int i = 0; i < 2; i++) {
#pragma unroll
        for (int half = 0; half < 2; half++) {
            int rowL = m0w + 16 * i + rowg + 8 * half;
            float p[4] = {0.f, 0.f, 0.f, 0.f};
#pragma unroll
            for (int j = 0; j < 8; j++) {
#pragma unroll
                for (int e = 0; e < 2; e++) {
                    int clw = 8 * j + 2 * q + e;
                    int cl = n0w + clw;
                    float val = (acc[i][j][half * 2 + e] + bv_s[cl]) * 0.125f;
                    p[clw >> 4] = fmaf(attn_s[rowL * 17 + (cl & 15)], val, p[clw >> 4]);
                }
            }
#pragma unroll
            for (int d = 0; d < 4; d++) {
                p[d] += __shfl_xor_sync(0xffffffffu, p[d], 1);
                p[d] += __shfl_xor_sync(0xffffffffu, p[d], 2);
            }
            if (q == 0) {
                red[rowL * 8 + wn * 4 + 0] = p[0];
                red[rowL * 8 + wn * 4 + 1] = p[1];
                red[rowL * 8 + wn * 4 + 2] = p[2];
                red[rowL * 8 + wn * 4 + 3] = p[3];
            }
        }
    }
    __syncthreads();

    // torch scramble scatter, fused with split-bf16 conversion:
    // u = h*2048 + s;  A2x[b*2048 + u/12][(u%12)*64 + d] = split(v)
    {
        int row = tid >> 1, part = tid & 1;
        float4 v = *reinterpret_cast<float4*>(&red[row * 8 + part * 4]);
        int t = m0 + row;
        int b = t >> 11, s = t & 2047;
        int u = h * 2048 + s;
        int jj = u / 12;
        int col0 = (u - jj * 12) * 64 + dbase + part * 4;
        float vf[4] = {v.x, v.y, v.z, v.w};
        __nv_bfloat16 hv[4], lv[4];
#pragma unroll
        for (int k = 0; k < 4; k++) {
            hv[k] = __float2bfloat16(vf[k]);
            lv[k] = __float2bfloat16(vf[k] - __bfloat162float(hv[k]));
        }
        size_t base = (size_t)(b * 2048 + jj) * K2 + col0;
        *reinterpret_cast<uint2*>(&g_A2x[base])       = *reinterpret_cast<uint2*>(hv);
        *reinterpret_cast<uint2*>(&g_A2x[base + 768]) = *reinterpret_cast<uint2*>(lv);
    }
}

// ---------------------------------------------------------------------------
extern "C" void kernel_launch(void* const* d_in, const int* in_sizes, int n_in,
                              void* d_out, int out_size)
{
    const float* query = (const float*)d_in[0];
    const float* value = (const float*)d_in[2];
    const float* rk    = (const float*)d_in[3];
    const float* rw    = (const float*)d_in[4];
    const float* Wq    = (const float*)d_in[5];
    const float* bq    = (const float*)d_in[6];
    const float* Wv    = (const float*)d_in[7];
    const float* bv    = (const float*)d_in[8];
    const float* Wo    = (const float*)d_in[9];
    const float* bo    = (const float*)d_in[10];
    float* out = (float*)d_out;

    cudaFuncSetAttribute(fused_v_mma_kernel,
                         cudaFuncAttributeMaxDynamicSharedMemorySize, FV_SMEM);
    cudaFuncSetAttribute(mma_gemm_kernel,
                         cudaFuncAttributeMaxDynamicSharedMemorySize, MG_SMEM);

    __nv_bfloat16 *A2, *A2x, *W2, *W2q, *W2o;
    float *qbuf;
    cudaGetSymbolAddress((void**)&A2,  g_A2);
    cudaGetSymbolAddress((void**)&A2x, g_A2x);
    cudaGetSymbolAddress((void**)&W2,  g_W2);
    cudaGetSymbolAddress((void**)&W2q, g_W2q);
    cudaGetSymbolAddress((void**)&W2o, g_W2o);
    cudaGetSymbolAddress((void**)&qbuf, g_q);

    // q-projection (split-bf16 tensor-core GEMM) + fuzzy attn
    convert_A_kernel<<<(T_TOK * E_DIM) / 256, 256>>>(query, A2x);
    convert_W_kernel<<<dim3(E_DIM / 32, E_DIM / 32), 256>>>(Wq, W2q, E_DIM);
    mma_gemm_kernel<<<dim3(E_DIM / 128, T_TOK / 128), 256, MG_SMEM>>>(
        A2x, W2q, bq, qbuf, 0.125f);
    attn_kernel<<<dim3(T_TOK / 32, HN), 512>>>(rk, rw);

    // fused value-path GEMM + rule reduction (writes split mid into A2x)
    convert_A_kernel<<<(T_TOK * E_DIM) / 256, 256>>>(value, A2);
    convert_W_kernel<<<dim3(ER / 32, E_DIM / 32), 256>>>(Wv, W2, ER);
    fused_v_mma_kernel<<<dim3(ER / 128, T_TOK / 128), 256, FV_SMEM>>>(bv);

    // output projection (split-bf16 tensor-core GEMM; A2x already split)
    convert_W_kernel<<<dim3(E_DIM / 32, E_DIM / 32), 256>>>(Wo, W2o, E_DIM);
    mma_gemm_kernel<<<dim3(E_DIM / 128, T_TOK / 128), 256, MG_SMEM>>>(
        A2x, W2o, bo, out, 1.0f);
}

// round 12
// speedup vs baseline: 1.1570x; 1.0303x over previous
#include <cuda_runtime.h>
#include <cuda_bf16.h>
#include <cstdint>

#define T_TOK 4096
#define E_DIM 768
#define HN 12
#define RN 16
#define HD 64
#define ER 12288
#define K3 2304          // split-bf16 concatenated K: [hi | hi | lo]
#define NCHUNK 36        // K3 / 64 halves per chunk

// ---------------------------------------------------------------------------
// Scratch (__device__ globals; allocation-free rule)
// ---------------------------------------------------------------------------
__device__ float g_q[T_TOK * E_DIM];
__device__ float g_attn[T_TOK * HN * RN];
__device__ __align__(128) __nv_bfloat16 g_A2[(size_t)T_TOK * K3];    // value  [Vh|Vh|Vl]
__device__ __align__(128) __nv_bfloat16 g_A2x[(size_t)T_TOK * K3];   // query, then mid (split, scrambled)
__device__ __align__(128) __nv_bfloat16 g_W2[(size_t)ER * K3];       // Wv  [Wh|Wl|Wh], [N,K] K-major
__device__ __align__(128) __nv_bfloat16 g_W2q[(size_t)E_DIM * K3];   // Wq
__device__ __align__(128) __nv_bfloat16 g_W2o[(size_t)E_DIM * K3];   // Wo

// ---------------------------------------------------------------------------
__device__ __forceinline__ uint32_t smem_u32(const void* p) {
    uint32_t a;
    asm("{ .reg .u64 t; cvta.to.shared.u64 t, %1; cvt.u32.u64 %0, t; }" : "=r"(a) : "l"(p));
    return a;
}

#define CP_ASYNC16(dst, src) \
    asm volatile("cp.async.cg.shared.global [%0], [%1], 16;" :: "r"(dst), "l"(src))
#define CP_COMMIT() asm volatile("cp.async.commit_group;" ::: "memory")

__device__ __forceinline__ void ldsm_x4(uint32_t& r0, uint32_t& r1, uint32_t& r2,
                                        uint32_t& r3, uint32_t addr) {
    asm volatile("ldmatrix.sync.aligned.m8n8.x4.shared.b16 {%0,%1,%2,%3}, [%4];"
                 : "=r"(r0), "=r"(r1), "=r"(r2), "=r"(r3) : "r"(addr));
}

__device__ __forceinline__ void mma_bf16(float* c, const uint32_t* a,
                                         uint32_t b0, uint32_t b1) {
    asm volatile(
        "mma.sync.aligned.m16n8k16.row.col.f32.bf16.bf16.f32 "
        "{%0,%1,%2,%3}, {%4,%5,%6,%7}, {%8,%9}, {%0,%1,%2,%3};"
        : "+f"(c[0]), "+f"(c[1]), "+f"(c[2]), "+f"(c[3])
        : "r"(a[0]), "r"(a[1]), "r"(a[2]), "r"(a[3]), "r"(b0), "r"(b1));
}

// ---------------------------------------------------------------------------
// Fuzzy membership + 16-wide softmax (proven round-7 version, unchanged)
// ---------------------------------------------------------------------------
__global__ __launch_bounds__(512) void attn_kernel(
    const float* __restrict__ rk, const float* __restrict__ rw)
{
    __shared__ float rkT[HD * RN];
    __shared__ float iwT[HD * RN];
    __shared__ float q_s[32 * 68];

    int tid = threadIdx.x;
    int t0 = blockIdx.x * 32;
    int h  = blockIdx.y;

#pragma unroll
    for (int it = 0; it < 2; it++) {
        int idx = tid + it * 512;
        int r = idx >> 6, d = idx & 63;
        float k = rk[h * (RN * HD) + idx];
        float w = rw[h * (RN * HD) + idx];
        rkT[d * RN + r] = k;
        iwT[d * RN + r] = 1.0f / (w * w);
    }
    {
        int row = tid >> 4, c = tid & 15;
        float4 v = *reinterpret_cast<const float4*>(
            &g_q[(size_t)(t0 + row) * E_DIM + h * HD + c * 4]);
        *reinterpret_cast<float4*>(&q_s[row * 68 + c * 4]) = v;
    }
    __syncthreads();

    int r  = tid & 15;
    int tl = tid >> 4;

    float s = 0.f;
#pragma unroll
    for (int d = 0; d < HD; d++) {
        float diff = q_s[tl * 68 + d] - rkT[d * RN + r];
        s = fmaf(diff * diff, iwT[d * RN + r], s);
    }
    float z = -0.5f * s * (1.0f / 64.0f);

    float m = z;
#pragma unroll
    for (int o = 8; o; o >>= 1) m = fmaxf(m, __shfl_xor_sync(0xffffffffu, m, o));
    float e = expf(z - m);
    float sum = e;
#pragma unroll
    for (int o = 8; o; o >>= 1) sum += __shfl_xor_sync(0xffffffffu, sum, o);

    g_attn[(size_t)(t0 + tl) * (HN * RN) + h * RN + r] = e / sum;
}

// ---------------------------------------------------------------------------
// Split-bf16 conversions — K3 [hi | hi | lo] layout (A) / [hi | lo | hi] (W)
// ---------------------------------------------------------------------------
__global__ __launch_bounds__(256) void convert_A_kernel(
    const float* __restrict__ src, __nv_bfloat16* __restrict__ dst)
{
    int idx = blockIdx.x * 256 + threadIdx.x;
    int t = idx / E_DIM, e = idx - t * E_DIM;
    float v = src[idx];
    __nv_bfloat16 hi = __float2bfloat16(v);
    __nv_bfloat16 lo = __float2bfloat16(v - __bfloat162float(hi));
    size_t base = (size_t)t * K3 + e;
    dst[base]        = hi;
    dst[base + 768]  = hi;
    dst[base + 1536] = lo;
}

__global__ __launch_bounds__(256) void convert_W_kernel(
    const float* __restrict__ W, __nv_bfloat16* __restrict__ dst, int ldW)
{
    __shared__ float s[32][33];
    int c0 = blockIdx.x * 32, e0 = blockIdx.y * 32;
    int tx = threadIdx.x & 31, ty = threadIdx.x >> 5;
#pragma unroll
    for (int it = 0; it < 4; it++) {
        int er = ty + it * 8;
        s[er][tx] = W[(size_t)(e0 + er) * ldW + c0 + tx];
    }
    __syncthreads();
#pragma unroll
    for (int it = 0; it < 4; it++) {
        int cr = ty + it * 8;
        float v = s[tx][cr];
        __nv_bfloat16 hi = __float2bfloat16(v);
        __nv_bfloat16 lo = __float2bfloat16(v - __bfloat162float(hi));
        size_t base = (size_t)(c0 + cr) * K3 + e0 + tx;
        dst[base]        = hi;
        dst[base + 768]  = lo;
        dst[base + 1536] = hi;
    }
}

// ---------------------------------------------------------------------------
// Generic split-bf16 mma.sync GEMM (M-tile 128): C = (A2 @ W2^T + bias)*scale
// ---------------------------------------------------------------------------
#define MG_SMEM (66560 + 1024)

__global__ __launch_bounds__(256) void mma_gemm_kernel(
    const __nv_bfloat16* __restrict__ A2, const __nv_bfloat16* __restrict__ W2,
    const float* __restrict__ bias, float* __restrict__ C, float scale)
{
    extern __shared__ char smraw[];
    char* sm = (char*)(((uintptr_t)smraw + 1023) & ~(uintptr_t)1023);
    uint32_t sbase = smem_u32(sm);
    float* bias_s = reinterpret_cast<float*>(sm + 65536);

    int tid = threadIdx.x;
    int lane = tid & 31, wid = tid >> 5;
    int wm = wid & 3, wn = wid >> 2;
    int m0w = wm * 32, n0w = wn * 64;
    int bx = blockIdx.x, by = blockIdx.y;
    int m0 = by * 128;

    const char* Ab = (const char*)A2 + (size_t)m0 * (K3 * 2);
    const char* Bb = (const char*)W2 + (size_t)(bx * 128) * (K3 * 2);

    if (tid < 128) bias_s[tid] = bias[bx * 128 + tid];

    auto load_chunk = [&](int kc, int buf) {
        long koff = (long)kc * 128;
        uint32_t Adst = sbase + buf * 16384u;
        uint32_t Bdst = sbase + 32768u + buf * 16384u;
#pragma unroll
        for (int it = 0; it < 4; it++) {
            int f = tid + it * 256;
            int row = f >> 3, cc = f & 7;
            CP_ASYNC16(Adst + row * 128 + (((cc ^ row) & 7) << 4),
                       Ab + (long)row * (K3 * 2) + koff + cc * 16);
        }
#pragma unroll
        for (int it = 0; it < 4; it++) {
            int f = tid + it * 256;
            int row = f >> 3, cc = f & 7;
            CP_ASYNC16(Bdst + row * 128 + (((cc ^ row) & 7) << 4),
                       Bb + (long)row * (K3 * 2) + koff + cc * 16);
        }
        CP_COMMIT();
    };

    float acc[2][8][4];
#pragma unroll
    for (int i = 0; i < 2; i++)
#pragma unroll
        for (int j = 0; j < 8; j++)
#pragma unroll
            for (int e = 0; e < 4; e++) acc[i][j][e] = 0.f;

    int xr = lane & 7;
    int aRow0 = m0w + (lane & 15);
    int aU = lane >> 4;
    int bRowB = n0w + (lane & 7) + ((lane >> 4) << 3);
    int bU = (lane >> 3) & 1;

    load_chunk(0, 0);

    for (int c = 0; c < NCHUNK; c++) {
        if (c + 1 < NCHUNK) {
            load_chunk(c + 1, (c + 1) & 1);
            asm volatile("cp.async.wait_group 1;" ::: "memory");
        } else {
            asm volatile("cp.async.wait_group 0;" ::: "memory");
        }
        __syncthreads();

        uint32_t Abase = sbase + (c & 1) * 16384u;
        uint32_t Bbase = sbase + 32768u + (c & 1) * 16384u;
#pragma unroll
        for (int s = 0; s < 4; s++) {
            uint32_t a[2][4];
#pragma unroll
            for (int i = 0; i < 2; i++) {
                int u = 2 * s + aU;
                uint32_t addr = Abase + (aRow0 + 16 * i) * 128 + ((u ^ xr) << 4);
                ldsm_x4(a[i][0], a[i][1], a[i][2], a[i][3], addr);
            }
            uint32_t b[4][4];
#pragma unroll
            for (int g = 0; g < 4; g++) {
                int u = 2 * s + bU;
                uint32_t addr = Bbase + (bRowB + 16 * g) * 128 + ((u ^ xr) << 4);
                ldsm_x4(b[g][0], b[g][1], b[g][2], b[g][3], addr);
            }
#pragma unroll
            for (int i = 0; i < 2; i++)
#pragma unroll
                for (int g = 0; g < 4; g++) {
                    mma_bf16(acc[i][2 * g],     a[i], b[g][0], b[g][1]);
                    mma_bf16(acc[i][2 * g + 1], a[i], b[g][2], b[g][3]);
                }
        }
        __syncthreads();
    }

#pragma unroll
    for (int i = 0; i < 2; i++) {
        int rowL = m0 + m0w + 16 * i + (lane >> 2);
#pragma unroll
        for (int j = 0; j < 8; j++) {
            int colL = n0w + 8 * j + 2 * (lane & 3);
            int colG = bx * 128 + colL;
            float2 v0 = make_float2((acc[i][j][0] + bias_s[colL]) * scale,
                                    (acc[i][j][1] + bias_s[colL + 1]) * scale);
            float2 v1 = make_float2((acc[i][j][2] + bias_s[colL]) * scale,
                                    (acc[i][j][3] + bias_s[colL + 1]) * scale);
            *reinterpret_cast<float2*>(&C[(size_t)rowL * E_DIM + colG]) = v0;
            *reinterpret_cast<float2*>(&C[(size_t)(rowL + 8) * E_DIM + colG]) = v1;
        }
    }
}

// ---------------------------------------------------------------------------
// Fused value-GEMM + rule reduction — round-7 proven geometry (M-128,
// 256 threads, 2-stage, 2 CTAs/SM, K3 storage); epilogue now writes
// split-bf16 mid directly into g_A2x (K3 [hi|hi|lo]) at the torch-scrambled
// position, eliminating g_mid and the third convert_A launch.
// smem layout (bytes, after 1024-align):
//   0      : A tiles  2 x 16384
//   32768  : B tiles  2 x 16384
//   65536  : attn_s   float[128][17]  (8704)
//   74240  : bv_s     float[128]      (512)
//   74752  : red      float[128][8]   (4096)
// ---------------------------------------------------------------------------
#define FV_SMEM (78848 + 1024)

__global__ __launch_bounds__(256) void fused_v_mma_kernel(const float* __restrict__ bv) {
    extern __shared__ char smraw[];
    char* sm = (char*)(((uintptr_t)smraw + 1023) & ~(uintptr_t)1023);
    uint32_t sbase = smem_u32(sm);
    float* attn_s = reinterpret_cast<float*>(sm + 65536);
    float* bv_s   = reinterpret_cast<float*>(sm + 74240);
    float* red    = reinterpret_cast<float*>(sm + 74752);

    int tid = threadIdx.x;
    int lane = tid & 31, wid = tid >> 5;
    int wm = wid & 3, wn = wid >> 2;
    int m0w = wm * 32, n0w = wn * 64;
    int bx = blockIdx.x, by = blockIdx.y;
    int m0 = by * 128;
    int h = bx >> 3;
    int dbase = (bx & 7) * 8;

    const char* Ab = (const char*)g_A2 + (size_t)m0 * (K3 * 2);
    const char* Bb = (const char*)g_W2 + (size_t)(bx * 128) * (K3 * 2);

#pragma unroll
    for (int it = 0; it < 8; it++) {
        int f = tid + it * 256;
        int row = f >> 4, r = f & 15;
        attn_s[row * 17 + r] = g_attn[(size_t)(m0 + row) * (HN * RN) + h * RN + r];
    }
    if (tid < 128) bv_s[tid] = bv[bx * 128 + tid];

    auto load_chunk = [&](int kc, int buf) {
        long koff = (long)kc * 128;
        uint32_t Adst = sbase + buf * 16384u;
        uint32_t Bdst = sbase + 32768u + buf * 16384u;
#pragma unroll
        for (int it = 0; it < 4; it++) {
            int f = tid + it * 256;
            int row = f >> 3, cc = f & 7;
            CP_ASYNC16(Adst + row * 128 + (((cc ^ row) & 7) << 4),
                       Ab + (long)row * (K3 * 2) + koff + cc * 16);
        }
#pragma unroll
        for (int it = 0; it < 4; it++) {
            int f = tid + it * 256;
            int row = f >> 3, cc = f & 7;
            CP_ASYNC16(Bdst + row * 128 + (((cc ^ row) & 7) << 4),
                       Bb + (long)row * (K3 * 2) + koff + cc * 16);
        }
        CP_COMMIT();
    };

    float acc[2][8][4];
#pragma unroll
    for (int i = 0; i < 2; i++)
#pragma unroll
        for (int j = 0; j < 8; j++)
#pragma unroll
            for (int e = 0; e < 4; e++) acc[i][j][e] = 0.f;

    int xr = lane & 7;
    int aRow0 = m0w + (lane & 15);
    int aU = lane >> 4;
    int bRowB = n0w + (lane & 7) + ((lane >> 4) << 3);
    int bU = (lane >> 3) & 1;

    load_chunk(0, 0);

    for (int c = 0; c < NCHUNK; c++) {
        if (c + 1 < NCHUNK) {
            load_chunk(c + 1, (c + 1) & 1);
            asm volatile("cp.async.wait_group 1;" ::: "memory");
        } else {
            asm volatile("cp.async.wait_group 0;" ::: "memory");
        }
        __syncthreads();

        uint32_t Abase = sbase + (c & 1) * 16384u;
        uint32_t Bbase = sbase + 32768u + (c & 1) * 16384u;
#pragma unroll
        for (int s = 0; s < 4; s++) {
            uint32_t a[2][4];
#pragma unroll
            for (int i = 0; i < 2; i++) {
                int u = 2 * s + aU;
                uint32_t addr = Abase + (aRow0 + 16 * i) * 128 + ((u ^ xr) << 4);
                ldsm_x4(a[i][0], a[i][1], a[i][2], a[i][3], addr);
            }
            uint32_t b[4][4];
#pragma unroll
            for (int g = 0; g < 4; g++) {
                int u = 2 * s + bU;
                uint32_t addr = Bbase + (bRowB + 16 * g) * 128 + ((u ^ xr) << 4);
                ldsm_x4(b[g][0], b[g][1], b[g][2], b[g][3], addr);
            }
#pragma unroll
            for (int i = 0; i < 2; i++)
#pragma unroll
                for (int g = 0; g < 4; g++) {
                    mma_bf16(acc[i][2 * g],     a[i], b[g][0], b[g][1]);
                    mma_bf16(acc[i][2 * g + 1], a[i], b[g][2], b[g][3]);
                }
        }
        __syncthreads();
    }

    // ---- Epilogue: attn-weighted rule reduction ----
    int q = lane & 3, rowg = lane >> 2;
#pragma unroll
    for (int i = 0; i < 2; i++) {
#pragma unroll
        for (int half = 0; half < 2; half++) {
            int rowL = m0w + 16 * i + rowg + 8 * half;
            float p[4] = {0.f, 0.f, 0.f, 0.f};
#pragma unroll
            for (int j = 0; j < 8; j++) {
#pragma unroll
                for (int e = 0; e < 2; e++) {
                    int clw = 8 * j + 2 * q + e;
                    int cl = n0w + clw;
                    float val = (acc[i][j][half * 2 + e] + bv_s[cl]) * 0.125f;
                    p[clw >> 4] = fmaf(attn_s[rowL * 17 + (cl & 15)], val, p[clw >> 4]);
                }
            }
#pragma unroll
            for (int d = 0; d < 4; d++) {
                p[d] += __shfl_xor_sync(0xffffffffu, p[d], 1);
                p[d] += __shfl_xor_sync(0xffffffffu, p[d], 2);
            }
            if (q == 0) {
                red[rowL * 8 + wn * 4 + 0] = p[0];
                red[rowL * 8 + wn * 4 + 1] = p[1];
                red[rowL * 8 + wn * 4 + 2] = p[2];
                red[rowL * 8 + wn * 4 + 3] = p[3];
            }
        }
    }
    __syncthreads();

    // torch scramble scatter, fused with split-bf16 conversion (K3 layout):
    // u = h*2048 + s;  A2x[b*2048 + u/12][(u%12)*64 + d] = {hi, hi, lo}
    {
        int row = tid >> 1, part = tid & 1;
        float4 v = *reinterpret_cast<float4*>(&red[row * 8 + part * 4]);
        int t = m0 + row;
        int b = t >> 11, s = t & 2047;
        int u = h * 2048 + s;
        int jj = u / 12;
        int col0 = (u - jj * 12) * 64 + dbase + part * 4;
        float vf[4] = {v.x, v.y, v.z, v.w};
        __nv_bfloat16 hv[4], lv[4];
#pragma unroll
        for (int k = 0; k < 4; k++) {
            hv[k] = __float2bfloat16(vf[k]);
            lv[k] = __float2bfloat16(vf[k] - __bfloat162float(hv[k]));
        }
        size_t base = (size_t)(b * 2048 + jj) * K3 + col0;
        *reinterpret_cast<uint2*>(&g_A2x[base])        = *reinterpret_cast<uint2*>(hv);
        *reinterpret_cast<uint2*>(&g_A2x[base + 768])  = *reinterpret_cast<uint2*>(hv);
        *reinterpret_cast<uint2*>(&g_A2x[base + 1536]) = *reinterpret_cast<uint2*>(lv);
    }
}

// ---------------------------------------------------------------------------
extern "C" void kernel_launch(void* const* d_in, const int* in_sizes, int n_in,
                              void* d_out, int out_size)
{
    const float* query = (const float*)d_in[0];
    const float* value = (const float*)d_in[2];
    const float* rk    = (const float*)d_in[3];
    const float* rw    = (const float*)d_in[4];
    const float* Wq    = (const float*)d_in[5];
    const float* bq    = (const float*)d_in[6];
    const float* Wv    = (const float*)d_in[7];
    const float* bv    = (const float*)d_in[8];
    const float* Wo    = (const float*)d_in[9];
    const float* bo    = (const float*)d_in[10];
    float* out = (float*)d_out;

    cudaFuncSetAttribute(fused_v_mma_kernel,
                         cudaFuncAttributeMaxDynamicSharedMemorySize, FV_SMEM);
    cudaFuncSetAttribute(mma_gemm_kernel,
                         cudaFuncAttributeMaxDynamicSharedMemorySize, MG_SMEM);

    __nv_bfloat16 *A2, *A2x, *W2, *W2q, *W2o;
    float *qbuf;
    cudaGetSymbolAddress((void**)&A2,  g_A2);
    cudaGetSymbolAddress((void**)&A2x, g_A2x);
    cudaGetSymbolAddress((void**)&W2,  g_W2);
    cudaGetSymbolAddress((void**)&W2q, g_W2q);
    cudaGetSymbolAddress((void**)&W2o, g_W2o);
    cudaGetSymbolAddress((void**)&qbuf, g_q);

    // q-projection (split-bf16 tensor-core GEMM) + fuzzy attn
    convert_A_kernel<<<(T_TOK * E_DIM) / 256, 256>>>(query, A2x);
    convert_W_kernel<<<dim3(E_DIM / 32, E_DIM / 32), 256>>>(Wq, W2q, E_DIM);
    mma_gemm_kernel<<<dim3(E_DIM / 128, T_TOK / 128), 256, MG_SMEM>>>(
        A2x, W2q, bq, qbuf, 0.125f);
    attn_kernel<<<dim3(T_TOK / 32, HN), 512>>>(rk, rw);

    // fused value-path GEMM + rule reduction (writes split mid into A2x)
    convert_A_kernel<<<(T_TOK * E_DIM) / 256, 256>>>(value, A2);
    convert_W_kernel<<<dim3(ER / 32, E_DIM / 32), 256>>>(Wv, W2, ER);
    fused_v_mma_kernel<<<dim3(ER / 128, T_TOK / 128), 256, FV_SMEM>>>(bv);

    // output projection (split-bf16 tensor-core GEMM; A2x already split)
    convert_W_kernel<<<dim3(E_DIM / 32, E_DIM / 32), 256>>>(Wo, W2o, E_DIM);
    mma_gemm_kernel<<<dim3(E_DIM / 128, T_TOK / 128), 256, MG_SMEM>>>(
        A2x, W2o, bo, out, 1.0f);
}

// round 13
// speedup vs baseline: 1.1965x; 1.0341x over previous
#include <cuda_runtime.h>
#include <cuda_bf16.h>
#include <cstdint>

#define T_TOK 4096
#define E_DIM 768
#define HN 12
#define RN 16
#define HD 64
#define ER 12288
#define K2 1536          // compact split-bf16 storage: [hi | lo]
#define NCHUNK 36        // linear 3-term schedule (mma_gemm)
#define NSUPER 24        // phased schedule (fused): 12 dual + 12 single

// ---------------------------------------------------------------------------
// Scratch (__device__ globals; allocation-free rule)
// ---------------------------------------------------------------------------
__device__ float g_q[T_TOK * E_DIM];
__device__ float g_attn[T_TOK * HN * RN];
__device__ __align__(128) __nv_bfloat16 g_A2[(size_t)T_TOK * K2];    // value  [Vh|Vl]
__device__ __align__(128) __nv_bfloat16 g_A2x[(size_t)T_TOK * K2];   // query, then mid (split, scrambled)
__device__ __align__(128) __nv_bfloat16 g_W2[(size_t)ER * K2];       // Wv  [Wh|Wl], [N,K] K-major
__device__ __align__(128) __nv_bfloat16 g_W2q[(size_t)E_DIM * K2];   // Wq
__device__ __align__(128) __nv_bfloat16 g_W2o[(size_t)E_DIM * K2];   // Wo

// linear 3-term schedule over compact storage (mma_gemm only):
//   c in [0,12): A hi, B hi   c in [12,24): A hi, B lo   c in [24,36): A lo, B hi
#define AOFF(c) (((c) < 12 ? (c) : (c) - 12) * 128L)
#define BOFF(c) (((c) < 24 ? (c) : (c) - 24) * 128L)

// ---------------------------------------------------------------------------
__device__ __forceinline__ uint32_t smem_u32(const void* p) {
    uint32_t a;
    asm("{ .reg .u64 t; cvta.to.shared.u64 t, %1; cvt.u32.u64 %0, t; }" : "=r"(a) : "l"(p));
    return a;
}

#define CP_ASYNC16(dst, src) \
    asm volatile("cp.async.cg.shared.global [%0], [%1], 16;" :: "r"(dst), "l"(src))
#define CP_COMMIT() asm volatile("cp.async.commit_group;" ::: "memory")

__device__ __forceinline__ void ldsm_x4(uint32_t& r0, uint32_t& r1, uint32_t& r2,
                                        uint32_t& r3, uint32_t addr) {
    asm volatile("ldmatrix.sync.aligned.m8n8.x4.shared.b16 {%0,%1,%2,%3}, [%4];"
                 : "=r"(r0), "=r"(r1), "=r"(r2), "=r"(r3) : "r"(addr));
}

__device__ __forceinline__ void mma_bf16(float* c, const uint32_t* a,
                                         uint32_t b0, uint32_t b1) {
    asm volatile(
        "mma.sync.aligned.m16n8k16.row.col.f32.bf16.bf16.f32 "
        "{%0,%1,%2,%3}, {%4,%5,%6,%7}, {%8,%9}, {%0,%1,%2,%3};"
        : "+f"(c[0]), "+f"(c[1]), "+f"(c[2]), "+f"(c[3])
        : "r"(a[0]), "r"(a[1]), "r"(a[2]), "r"(a[3]), "r"(b0), "r"(b1));
}

// ---------------------------------------------------------------------------
// Fuzzy membership + 16-wide softmax (proven, unchanged)
// ---------------------------------------------------------------------------
__global__ __launch_bounds__(512) void attn_kernel(
    const float* __restrict__ rk, const float* __restrict__ rw)
{
    __shared__ float rkT[HD * RN];
    __shared__ float iwT[HD * RN];
    __shared__ float q_s[32 * 68];

    int tid = threadIdx.x;
    int t0 = blockIdx.x * 32;
    int h  = blockIdx.y;

#pragma unroll
    for (int it = 0; it < 2; it++) {
        int idx = tid + it * 512;
        int r = idx >> 6, d = idx & 63;
        float k = rk[h * (RN * HD) + idx];
        float w = rw[h * (RN * HD) + idx];
        rkT[d * RN + r] = k;
        iwT[d * RN + r] = 1.0f / (w * w);
    }
    {
        int row = tid >> 4, c = tid & 15;
        float4 v = *reinterpret_cast<const float4*>(
            &g_q[(size_t)(t0 + row) * E_DIM + h * HD + c * 4]);
        *reinterpret_cast<float4*>(&q_s[row * 68 + c * 4]) = v;
    }
    __syncthreads();

    int r  = tid & 15;
    int tl = tid >> 4;

    float s = 0.f;
#pragma unroll
    for (int d = 0; d < HD; d++) {
        float diff = q_s[tl * 68 + d] - rkT[d * RN + r];
        s = fmaf(diff * diff, iwT[d * RN + r], s);
    }
    float z = -0.5f * s * (1.0f / 64.0f);

    float m = z;
#pragma unroll
    for (int o = 8; o; o >>= 1) m = fmaxf(m, __shfl_xor_sync(0xffffffffu, m, o));
    float e = expf(z - m);
    float sum = e;
#pragma unroll
    for (int o = 8; o; o >>= 1) sum += __shfl_xor_sync(0xffffffffu, sum, o);

    g_attn[(size_t)(t0 + tl) * (HN * RN) + h * RN + r] = e / sum;
}

// ---------------------------------------------------------------------------
// Split-bf16 conversions — compact [hi | lo] (proven round-10 versions)
// ---------------------------------------------------------------------------
__global__ __launch_bounds__(256) void convert_A_kernel(
    const float* __restrict__ src, __nv_bfloat16* __restrict__ dst)
{
    int idx = blockIdx.x * 256 + threadIdx.x;
    int t = idx / E_DIM, e = idx - t * E_DIM;
    float v = src[idx];
    __nv_bfloat16 hi = __float2bfloat16(v);
    __nv_bfloat16 lo = __float2bfloat16(v - __bfloat162float(hi));
    size_t base = (size_t)t * K2 + e;
    dst[base]       = hi;
    dst[base + 768] = lo;
}

__global__ __launch_bounds__(256) void convert_W_kernel(
    const float* __restrict__ W, __nv_bfloat16* __restrict__ dst, int ldW)
{
    __shared__ float s[32][33];
    int c0 = blockIdx.x * 32, e0 = blockIdx.y * 32;
    int tx = threadIdx.x & 31, ty = threadIdx.x >> 5;
#pragma unroll
    for (int it = 0; it < 4; it++) {
        int er = ty + it * 8;
        s[er][tx] = W[(size_t)(e0 + er) * ldW + c0 + tx];
    }
    __syncthreads();
#pragma unroll
    for (int it = 0; it < 4; it++) {
        int cr = ty + it * 8;
        float v = s[tx][cr];
        __nv_bfloat16 hi = __float2bfloat16(v);
        __nv_bfloat16 lo = __float2bfloat16(v - __bfloat162float(hi));
        size_t base = (size_t)(c0 + cr) * K2 + e0 + tx;
        dst[base]       = hi;
        dst[base + 768] = lo;
    }
}

// ---------------------------------------------------------------------------
// Generic split-bf16 mma.sync GEMM (K2 + AOFF/BOFF; proven round-10 version)
// ---------------------------------------------------------------------------
#define MG_SMEM (66560 + 1024)

__global__ __launch_bounds__(256) void mma_gemm_kernel(
    const __nv_bfloat16* __restrict__ A2, const __nv_bfloat16* __restrict__ W2,
    const float* __restrict__ bias, float* __restrict__ C, float scale)
{
    extern __shared__ char smraw[];
    char* sm = (char*)(((uintptr_t)smraw + 1023) & ~(uintptr_t)1023);
    uint32_t sbase = smem_u32(sm);
    float* bias_s = reinterpret_cast<float*>(sm + 65536);

    int tid = threadIdx.x;
    int lane = tid & 31, wid = tid >> 5;
    int wm = wid & 3, wn = wid >> 2;
    int m0w = wm * 32, n0w = wn * 64;
    int bx = blockIdx.x, by = blockIdx.y;
    int m0 = by * 128;

    const char* Ab = (const char*)A2 + (size_t)m0 * (K2 * 2);
    const char* Bb = (const char*)W2 + (size_t)(bx * 128) * (K2 * 2);

    if (tid < 128) bias_s[tid] = bias[bx * 128 + tid];

    auto load_chunk = [&](int kc, int buf) {
        long ako = AOFF(kc), bko = BOFF(kc);
        uint32_t Adst = sbase + buf * 16384u;
        uint32_t Bdst = sbase + 32768u + buf * 16384u;
#pragma unroll
        for (int it = 0; it < 4; it++) {
            int f = tid + it * 256;
            int row = f >> 3, cc = f & 7;
            CP_ASYNC16(Adst + row * 128 + (((cc ^ row) & 7) << 4),
                       Ab + (long)row * (K2 * 2) + ako + cc * 16);
        }
#pragma unroll
        for (int it = 0; it < 4; it++) {
            int f = tid + it * 256;
            int row = f >> 3, cc = f & 7;
            CP_ASYNC16(Bdst + row * 128 + (((cc ^ row) & 7) << 4),
                       Bb + (long)row * (K2 * 2) + bko + cc * 16);
        }
        CP_COMMIT();
    };

    float acc[2][8][4];
#pragma unroll
    for (int i = 0; i < 2; i++)
#pragma unroll
        for (int j = 0; j < 8; j++)
#pragma unroll
            for (int e = 0; e < 4; e++) acc[i][j][e] = 0.f;

    int xr = lane & 7;
    int aRow0 = m0w + (lane & 15);
    int aU = lane >> 4;
    int bRowB = n0w + (lane & 7) + ((lane >> 4) << 3);
    int bU = (lane >> 3) & 1;

    load_chunk(0, 0);

    for (int c = 0; c < NCHUNK; c++) {
        if (c + 1 < NCHUNK) {
            load_chunk(c + 1, (c + 1) & 1);
            asm volatile("cp.async.wait_group 1;" ::: "memory");
        } else {
            asm volatile("cp.async.wait_group 0;" ::: "memory");
        }
        __syncthreads();

        uint32_t Abase = sbase + (c & 1) * 16384u;
        uint32_t Bbase = sbase + 32768u + (c & 1) * 16384u;
#pragma unroll
        for (int s = 0; s < 4; s++) {
            uint32_t a[2][4];
#pragma unroll
            for (int i = 0; i < 2; i++) {
                int u = 2 * s + aU;
                uint32_t addr = Abase + (aRow0 + 16 * i) * 128 + ((u ^ xr) << 4);
                ldsm_x4(a[i][0], a[i][1], a[i][2], a[i][3], addr);
            }
            uint32_t b[4][4];
#pragma unroll
            for (int g = 0; g < 4; g++) {
                int u = 2 * s + bU;
                uint32_t addr = Bbase + (bRowB + 16 * g) * 128 + ((u ^ xr) << 4);
                ldsm_x4(b[g][0], b[g][1], b[g][2], b[g][3], addr);
            }
#pragma unroll
            for (int i = 0; i < 2; i++)
#pragma unroll
                for (int g = 0; g < 4; g++) {
                    mma_bf16(acc[i][2 * g],     a[i], b[g][0], b[g][1]);
                    mma_bf16(acc[i][2 * g + 1], a[i], b[g][2], b[g][3]);
                }
        }
        __syncthreads();
    }

#pragma unroll
    for (int i = 0; i < 2; i++) {
        int rowL = m0 + m0w + 16 * i + (lane >> 2);
#pragma unroll
        for (int j = 0; j < 8; j++) {
            int colL = n0w + 8 * j + 2 * (lane & 3);
            int colG = bx * 128 + colL;
            float2 v0 = make_float2((acc[i][j][0] + bias_s[colL]) * scale,
                                    (acc[i][j][1] + bias_s[colL + 1]) * scale);
            float2 v1 = make_float2((acc[i][j][2] + bias_s[colL]) * scale,
                                    (acc[i][j][3] + bias_s[colL + 1]) * scale);
            *reinterpret_cast<float2*>(&C[(size_t)rowL * E_DIM + colG]) = v0;
            *reinterpret_cast<float2*>(&C[(size_t)(rowL + 8) * E_DIM + colG]) = v1;
        }
    }
}

// ---------------------------------------------------------------------------
// Fused value-GEMM + rule reduction — term-phased schedule.
// Phase 1 (sc 0..11):  stage {Ah, Bh, Bl}; compute Ah*Bh + Ah*Bl (A frags reused)
// Phase 2 (sc 12..23): stage {Al, Bh};     compute Al*Bh
// M-128, 256 threads, double-buffered 2 x 48KB -> 2 CTAs/SM.
// Epilogue: rule reduction + torch-scramble scatter + split-bf16 mid -> g_A2x.
// smem: stage 2x49152 @0 | attn_s @98304 (8704) | bv @107008 (512) |
//       red @107520 (4096) -> 111616
// ---------------------------------------------------------------------------
#define FV_SMEM (111616 + 1024)

__global__ __launch_bounds__(256) void fused_v_mma_kernel(const float* __restrict__ bv) {
    extern __shared__ char smraw[];
    char* sm = (char*)(((uintptr_t)smraw + 1023) & ~(uintptr_t)1023);
    uint32_t sbase = smem_u32(sm);
    float* attn_s = reinterpret_cast<float*>(sm + 98304);
    float* bv_s   = reinterpret_cast<float*>(sm + 107008);
    float* red    = reinterpret_cast<float*>(sm + 107520);

    int tid = threadIdx.x;
    int lane = tid & 31, wid = tid >> 5;
    int wm = wid & 3, wn = wid >> 2;
    int m0w = wm * 32, n0w = wn * 64;
    int bx = blockIdx.x, by = blockIdx.y;
    int m0 = by * 128;
    int h = bx >> 3;
    int dbase = (bx & 7) * 8;

    const char* Ab = (const char*)g_A2 + (size_t)m0 * (K2 * 2);
    const char* Bb = (const char*)g_W2 + (size_t)(bx * 128) * (K2 * 2);

#pragma unroll
    for (int it = 0; it < 8; it++) {
        int f = tid + it * 256;
        int row = f >> 4, r = f & 15;
        attn_s[row * 17 + r] = g_attn[(size_t)(m0 + row) * (HN * RN) + h * RN + r];
    }
    if (tid < 128) bv_s[tid] = bv[bx * 128 + tid];

    // stage slots within a buffer: A @ +0, B0 @ +16384, B1 @ +32768
    auto load_super = [&](int sc, int buf) {
        uint32_t Ad = sbase + buf * 49152u;
        uint32_t B0 = Ad + 16384u;
        uint32_t B1 = Ad + 32768u;
        if (sc < 12) {
            long ao  = (long)sc * 128;          // A hi
            long bo0 = (long)sc * 128;          // B hi
            long bo1 = 1536 + (long)sc * 128;   // B lo
#pragma unroll
            for (int it = 0; it < 4; it++) {
                int f = tid + it * 256;
                int row = f >> 3, cc = f & 7;
                uint32_t so = row * 128 + (((cc ^ row) & 7) << 4);
                long go = (long)row * (K2 * 2);
                CP_ASYNC16(Ad + so, Ab + go + ao  + cc * 16);
                CP_ASYNC16(B0 + so, Bb + go + bo0 + cc * 16);
                CP_ASYNC16(B1 + so, Bb + go + bo1 + cc * 16);
            }
        } else {
            int i = sc - 12;
            long ao  = 1536 + (long)i * 128;    // A lo
            long bo0 = (long)i * 128;           // B hi
#pragma unroll
            for (int it = 0; it < 4; it++) {
                int f = tid + it * 256;
                int row = f >> 3, cc = f & 7;
                uint32_t so = row * 128 + (((cc ^ row) & 7) << 4);
                long go = (long)row * (K2 * 2);
                CP_ASYNC16(Ad + so, Ab + go + ao  + cc * 16);
                CP_ASYNC16(B0 + so, Bb + go + bo0 + cc * 16);
            }
        }
        CP_COMMIT();
    };

    float acc[2][8][4];
#pragma unroll
    for (int i = 0; i < 2; i++)
#pragma unroll
        for (int j = 0; j < 8; j++)
#pragma unroll
            for (int e = 0; e < 4; e++) acc[i][j][e] = 0.f;

    int xr = lane & 7;
    int aRow0 = m0w + (lane & 15);
    int aU = lane >> 4;
    int bRowB = n0w + (lane & 7) + ((lane >> 4) << 3);
    int bU = (lane >> 3) & 1;

    load_super(0, 0);

    for (int sc = 0; sc < NSUPER; sc++) {
        if (sc + 1 < NSUPER) {
            load_super(sc + 1, (sc + 1) & 1);
            asm volatile("cp.async.wait_group 1;" ::: "memory");
        } else {
            asm volatile("cp.async.wait_group 0;" ::: "memory");
        }
        __syncthreads();

        uint32_t Abase = sbase + (sc & 1) * 49152u;
        uint32_t B0base = Abase + 16384u;
        uint32_t B1base = Abase + 32768u;
        bool dual = (sc < 12);
#pragma unroll
        for (int s = 0; s < 4; s++) {
            uint32_t a[2][4];
#pragma unroll
            for (int i = 0; i < 2; i++) {
                int u = 2 * s + aU;
                uint32_t addr = Abase + (aRow0 + 16 * i) * 128 + ((u ^ xr) << 4);
                ldsm_x4(a[i][0], a[i][1], a[i][2], a[i][3], addr);
            }
            // segment B0 (always)
            {
                uint32_t b[4][4];
#pragma unroll
                for (int g = 0; g < 4; g++) {
                    int u = 2 * s + bU;
                    uint32_t addr = B0base + (bRowB + 16 * g) * 128 + ((u ^ xr) << 4);
                    ldsm_x4(b[g][0], b[g][1], b[g][2], b[g][3], addr);
                }
#pragma unroll
                for (int i = 0; i < 2; i++)
#pragma unroll
                    for (int g = 0; g < 4; g++) {
                        mma_bf16(acc[i][2 * g],     a[i], b[g][0], b[g][1]);
                        mma_bf16(acc[i][2 * g + 1], a[i], b[g][2], b[g][3]);
                    }
            }
            // segment B1 (phase 1 only) — reuses the same A fragments
            if (dual) {
                uint32_t b[4][4];
#pragma unroll
                for (int g = 0; g < 4; g++) {
                    int u = 2 * s + bU;
                    uint32_t addr = B1base + (bRowB + 16 * g) * 128 + ((u ^ xr) << 4);
                    ldsm_x4(b[g][0], b[g][1], b[g][2], b[g][3], addr);
                }
#pragma unroll
                for (int i = 0; i < 2; i++)
#pragma unroll
                    for (int g = 0; g < 4; g++) {
                        mma_bf16(acc[i][2 * g],     a[i], b[g][0], b[g][1]);
                        mma_bf16(acc[i][2 * g + 1], a[i], b[g][2], b[g][3]);
                    }
            }
        }
        __syncthreads();
    }

    // ---- Epilogue: attn-weighted rule reduction ----
    int q = lane & 3, rowg = lane >> 2;
#pragma unroll
    for (int i = 0; i < 2; i++) {
#pragma unroll
        for (int half = 0; half < 2; half++) {
            int rowL = m0w + 16 * i + rowg + 8 * half;
            float p[4] = {0.f, 0.f, 0.f, 0.f};
#pragma unroll
            for (int j = 0; j < 8; j++) {
#pragma unroll
                for (int e = 0; e < 2; e++) {
                    int clw = 8 * j + 2 * q + e;
                    int cl = n0w + clw;
                    float val = (acc[i][j][half * 2 + e] + bv_s[cl]) * 0.125f;
                    p[clw >> 4] = fmaf(attn_s[rowL * 17 + (cl & 15)], val, p[clw >> 4]);
                }
            }
#pragma unroll
            for (int d = 0; d < 4; d++) {
                p[d] += __shfl_xor_sync(0xffffffffu, p[d], 1);
                p[d] += __shfl_xor_sync(0xffffffffu, p[d], 2);
            }
            if (q == 0) {
                red[rowL * 8 + wn * 4 + 0] = p[0];
                red[rowL * 8 + wn * 4 + 1] = p[1];
                red[rowL * 8 + wn * 4 + 2] = p[2];
                red[rowL * 8 + wn * 4 + 3] = p[3];
            }
        }
    }
    __syncthreads();

    // torch scramble scatter, fused with split-bf16 conversion (K2 layout):
    // u = h*2048 + s;  A2x[b*2048 + u/12][(u%12)*64 + d] = {hi, lo}
    {
        int row = tid >> 1, part = tid & 1;
        float4 v = *reinterpret_cast<float4*>(&red[row * 8 + part * 4]);
        int t = m0 + row;
        int b = t >> 11, s = t & 2047;
        int u = h * 2048 + s;
        int jj = u / 12;
        int col0 = (u - jj * 12) * 64 + dbase + part * 4;
        float vf[4] = {v.x, v.y, v.z, v.w};
        __nv_bfloat16 hv[4], lv[4];
#pragma unroll
        for (int k = 0; k < 4; k++) {
            hv[k] = __float2bfloat16(vf[k]);
            lv[k] = __float2bfloat16(vf[k] - __bfloat162float(hv[k]));
        }
        size_t base = (size_t)(b * 2048 + jj) * K2 + col0;
        *reinterpret_cast<uint2*>(&g_A2x[base])       = *reinterpret_cast<uint2*>(hv);
        *reinterpret_cast<uint2*>(&g_A2x[base + 768]) = *reinterpret_cast<uint2*>(lv);
    }
}

// ---------------------------------------------------------------------------
extern "C" void kernel_launch(void* const* d_in, const int* in_sizes, int n_in,
                              void* d_out, int out_size)
{
    const float* query = (const float*)d_in[0];
    const float* value = (const float*)d_in[2];
    const float* rk    = (const float*)d_in[3];
    const float* rw    = (const float*)d_in[4];
    const float* Wq    = (const float*)d_in[5];
    const float* bq    = (const float*)d_in[6];
    const float* Wv    = (const float*)d_in[7];
    const float* bv    = (const float*)d_in[8];
    const float* Wo    = (const float*)d_in[9];
    const float* bo    = (const float*)d_in[10];
    float* out = (float*)d_out;

    cudaFuncSetAttribute(fused_v_mma_kernel,
                         cudaFuncAttributeMaxDynamicSharedMemorySize, FV_SMEM);
    cudaFuncSetAttribute(mma_gemm_kernel,
                         cudaFuncAttributeMaxDynamicSharedMemorySize, MG_SMEM);

    __nv_bfloat16 *A2, *A2x, *W2, *W2q, *W2o;
    float *qbuf;
    cudaGetSymbolAddress((void**)&A2,  g_A2);
    cudaGetSymbolAddress((void**)&A2x, g_A2x);
    cudaGetSymbolAddress((void**)&W2,  g_W2);
    cudaGetSymbolAddress((void**)&W2q, g_W2q);
    cudaGetSymbolAddress((void**)&W2o, g_W2o);
    cudaGetSymbolAddress((void**)&qbuf, g_q);

    // q-projection (split-bf16 tensor-core GEMM) + fuzzy attn
    convert_A_kernel<<<(T_TOK * E_DIM) / 256, 256>>>(query, A2x);
    convert_W_kernel<<<dim3(E_DIM / 32, E_DIM / 32), 256>>>(Wq, W2q, E_DIM);
    mma_gemm_kernel<<<dim3(E_DIM / 128, T_TOK / 128), 256, MG_SMEM>>>(
        A2x, W2q, bq, qbuf, 0.125f);
    attn_kernel<<<dim3(T_TOK / 32, HN), 512>>>(rk, rw);

    // fused value-path GEMM + rule reduction (writes split mid into A2x)
    convert_A_kernel<<<(T_TOK * E_DIM) / 256, 256>>>(value, A2);
    convert_W_kernel<<<dim3(ER / 32, E_DIM / 32), 256>>>(Wv, W2, ER);
    fused_v_mma_kernel<<<dim3(ER / 128, T_TOK / 128), 256, FV_SMEM>>>(bv);

    // output projection (split-bf16 tensor-core GEMM; A2x already split)
    convert_W_kernel<<<dim3(E_DIM / 32, E_DIM / 32), 256>>>(Wo, W2o, E_DIM);
    mma_gemm_kernel<<<dim3(E_DIM / 128, T_TOK / 128), 256, MG_SMEM>>>(
        A2x, W2o, bo, out, 1.0f);
}

// round 14
// speedup vs baseline: 1.2169x; 1.0171x over previous
#include <cuda_runtime.h>
#include <cuda_bf16.h>
#include <cstdint>

#define T_TOK 4096
#define E_DIM 768
#define HN 12
#define RN 16
#define HD 64
#define ER 12288
#define K2 1536          // compact split-bf16 storage: [hi | lo]
#define NSUPER 24        // phased schedule: 12 dual + 12 single superchunks

// ---------------------------------------------------------------------------
// Scratch (__device__ globals; allocation-free rule)
// ---------------------------------------------------------------------------
__device__ float g_q[T_TOK * E_DIM];
__device__ float g_attn[T_TOK * HN * RN];
__device__ __align__(128) __nv_bfloat16 g_A2[(size_t)T_TOK * K2];    // value  [Vh|Vl]
__device__ __align__(128) __nv_bfloat16 g_A2x[(size_t)T_TOK * K2];   // query, then mid (split, scrambled)
__device__ __align__(128) __nv_bfloat16 g_W2[(size_t)ER * K2];       // Wv  [Wh|Wl], [N,K] K-major
__device__ __align__(128) __nv_bfloat16 g_W2q[(size_t)E_DIM * K2];   // Wq
__device__ __align__(128) __nv_bfloat16 g_W2o[(size_t)E_DIM * K2];   // Wo

// ---------------------------------------------------------------------------
__device__ __forceinline__ uint32_t smem_u32(const void* p) {
    uint32_t a;
    asm("{ .reg .u64 t; cvta.to.shared.u64 t, %1; cvt.u32.u64 %0, t; }" : "=r"(a) : "l"(p));
    return a;
}

#define CP_ASYNC16(dst, src) \
    asm volatile("cp.async.cg.shared.global [%0], [%1], 16;" :: "r"(dst), "l"(src))
#define CP_COMMIT() asm volatile("cp.async.commit_group;" ::: "memory")

__device__ __forceinline__ void ldsm_x4(uint32_t& r0, uint32_t& r1, uint32_t& r2,
                                        uint32_t& r3, uint32_t addr) {
    asm volatile("ldmatrix.sync.aligned.m8n8.x4.shared.b16 {%0,%1,%2,%3}, [%4];"
                 : "=r"(r0), "=r"(r1), "=r"(r2), "=r"(r3) : "r"(addr));
}

__device__ __forceinline__ void mma_bf16(float* c, const uint32_t* a,
                                         uint32_t b0, uint32_t b1) {
    asm volatile(
        "mma.sync.aligned.m16n8k16.row.col.f32.bf16.bf16.f32 "
        "{%0,%1,%2,%3}, {%4,%5,%6,%7}, {%8,%9}, {%0,%1,%2,%3};"
        : "+f"(c[0]), "+f"(c[1]), "+f"(c[2]), "+f"(c[3])
        : "r"(a[0]), "r"(a[1]), "r"(a[2]), "r"(a[3]), "r"(b0), "r"(b1));
}

// ---------------------------------------------------------------------------
// Fuzzy membership + 16-wide softmax (proven, unchanged)
// ---------------------------------------------------------------------------
__global__ __launch_bounds__(512) void attn_kernel(
    const float* __restrict__ rk, const float* __restrict__ rw)
{
    __shared__ float rkT[HD * RN];
    __shared__ float iwT[HD * RN];
    __shared__ float q_s[32 * 68];

    int tid = threadIdx.x;
    int t0 = blockIdx.x * 32;
    int h  = blockIdx.y;

#pragma unroll
    for (int it = 0; it < 2; it++) {
        int idx = tid + it * 512;
        int r = idx >> 6, d = idx & 63;
        float k = rk[h * (RN * HD) + idx];
        float w = rw[h * (RN * HD) + idx];
        rkT[d * RN + r] = k;
        iwT[d * RN + r] = 1.0f / (w * w);
    }
    {
        int row = tid >> 4, c = tid & 15;
        float4 v = *reinterpret_cast<const float4*>(
            &g_q[(size_t)(t0 + row) * E_DIM + h * HD + c * 4]);
        *reinterpret_cast<float4*>(&q_s[row * 68 + c * 4]) = v;
    }
    __syncthreads();

    int r  = tid & 15;
    int tl = tid >> 4;

    float s = 0.f;
#pragma unroll
    for (int d = 0; d < HD; d++) {
        float diff = q_s[tl * 68 + d] - rkT[d * RN + r];
        s = fmaf(diff * diff, iwT[d * RN + r], s);
    }
    float z = -0.5f * s * (1.0f / 64.0f);

    float m = z;
#pragma unroll
    for (int o = 8; o; o >>= 1) m = fmaxf(m, __shfl_xor_sync(0xffffffffu, m, o));
    float e = expf(z - m);
    float sum = e;
#pragma unroll
    for (int o = 8; o; o >>= 1) sum += __shfl_xor_sync(0xffffffffu, sum, o);

    g_attn[(size_t)(t0 + tl) * (HN * RN) + h * RN + r] = e / sum;
}

// ---------------------------------------------------------------------------
// Split-bf16 conversions — merged launches
// convert_A2: blockIdx < half -> query->A2x ; else value->A2
// ---------------------------------------------------------------------------
__global__ __launch_bounds__(256) void convert_A2_kernel(
    const float* __restrict__ query, const float* __restrict__ value)
{
    const int half = (T_TOK * E_DIM) / 256;
    int bb = blockIdx.x;
    const float* src = (bb < half) ? query : value;
    __nv_bfloat16* dst;
    if (bb < half) { dst = g_A2x; } else { dst = g_A2; bb -= half; }
    int idx = bb * 256 + threadIdx.x;
    int t = idx / E_DIM, e = idx - t * E_DIM;
    float v = src[idx];
    __nv_bfloat16 hi = __float2bfloat16(v);
    __nv_bfloat16 lo = __float2bfloat16(v - __bfloat162float(hi));
    size_t base = (size_t)t * K2 + e;
    dst[base]       = hi;
    dst[base + 768] = lo;
}

// convert_W: grid.z selects weight (0 = Wv, used alone; for Wq/Wo merged: 0=Wq,1=Wo)
__global__ __launch_bounds__(256) void convert_W_kernel(
    const float* __restrict__ W, __nv_bfloat16* __restrict__ dst, int ldW)
{
    __shared__ float s[32][33];
    int c0 = blockIdx.x * 32, e0 = blockIdx.y * 32;
    int tx = threadIdx.x & 31, ty = threadIdx.x >> 5;
#pragma unroll
    for (int it = 0; it < 4; it++) {
        int er = ty + it * 8;
        s[er][tx] = W[(size_t)(e0 + er) * ldW + c0 + tx];
    }
    __syncthreads();
#pragma unroll
    for (int it = 0; it < 4; it++) {
        int cr = ty + it * 8;
        float v = s[tx][cr];
        __nv_bfloat16 hi = __float2bfloat16(v);
        __nv_bfloat16 lo = __float2bfloat16(v - __bfloat162float(hi));
        size_t base = (size_t)(c0 + cr) * K2 + e0 + tx;
        dst[base]       = hi;
        dst[base + 768] = lo;
    }
}

__global__ __launch_bounds__(256) void convert_Wqo_kernel(
    const float* __restrict__ Wq, const float* __restrict__ Wo)
{
    __shared__ float s[32][33];
    const float* W = (blockIdx.z == 0) ? Wq : Wo;
    __nv_bfloat16* dst = (blockIdx.z == 0) ? g_W2q : g_W2o;
    int c0 = blockIdx.x * 32, e0 = blockIdx.y * 32;
    int tx = threadIdx.x & 31, ty = threadIdx.x >> 5;
#pragma unroll
    for (int it = 0; it < 4; it++) {
        int er = ty + it * 8;
        s[er][tx] = W[(size_t)(e0 + er) * E_DIM + c0 + tx];
    }
    __syncthreads();
#pragma unroll
    for (int it = 0; it < 4; it++) {
        int cr = ty + it * 8;
        float v = s[tx][cr];
        __nv_bfloat16 hi = __float2bfloat16(v);
        __nv_bfloat16 lo = __float2bfloat16(v - __bfloat162float(hi));
        size_t base = (size_t)(c0 + cr) * K2 + e0 + tx;
        dst[base]       = hi;
        dst[base + 768] = lo;
    }
}

// ---------------------------------------------------------------------------
// Generic split-bf16 mma.sync GEMM — term-phased schedule (mirrors fused):
// Phase 1 (sc 0..11):  stage {Ah, Bh, Bl}; compute Ah*Bh + Ah*Bl
// Phase 2 (sc 12..23): stage {Al, Bh};     compute Al*Bh
// smem: stage 2x49152 @0 | bias @98304 (512) -> 98816
// ---------------------------------------------------------------------------
#define MG_SMEM (98816 + 1024)

__global__ __launch_bounds__(256) void mma_gemm_kernel(
    const __nv_bfloat16* __restrict__ A2, const __nv_bfloat16* __restrict__ W2,
    const float* __restrict__ bias, float* __restrict__ C, float scale)
{
    extern __shared__ char smraw[];
    char* sm = (char*)(((uintptr_t)smraw + 1023) & ~(uintptr_t)1023);
    uint32_t sbase = smem_u32(sm);
    float* bias_s = reinterpret_cast<float*>(sm + 98304);

    int tid = threadIdx.x;
    int lane = tid & 31, wid = tid >> 5;
    int wm = wid & 3, wn = wid >> 2;
    int m0w = wm * 32, n0w = wn * 64;
    int bx = blockIdx.x, by = blockIdx.y;
    int m0 = by * 128;

    const char* Ab = (const char*)A2 + (size_t)m0 * (K2 * 2);
    const char* Bb = (const char*)W2 + (size_t)(bx * 128) * (K2 * 2);

    if (tid < 128) bias_s[tid] = bias[bx * 128 + tid];

    auto load_super = [&](int sc, int buf) {
        uint32_t Ad = sbase + buf * 49152u;
        uint32_t B0 = Ad + 16384u;
        uint32_t B1 = Ad + 32768u;
        if (sc < 12) {
            long ao  = (long)sc * 128;
            long bo0 = (long)sc * 128;
            long bo1 = 1536 + (long)sc * 128;
#pragma unroll
            for (int it = 0; it < 4; it++) {
                int f = tid + it * 256;
                int row = f >> 3, cc = f & 7;
                uint32_t so = row * 128 + (((cc ^ row) & 7) << 4);
                long go = (long)row * (K2 * 2);
                CP_ASYNC16(Ad + so, Ab + go + ao  + cc * 16);
                CP_ASYNC16(B0 + so, Bb + go + bo0 + cc * 16);
                CP_ASYNC16(B1 + so, Bb + go + bo1 + cc * 16);
            }
        } else {
            int i = sc - 12;
            long ao  = 1536 + (long)i * 128;
            long bo0 = (long)i * 128;
#pragma unroll
            for (int it = 0; it < 4; it++) {
                int f = tid + it * 256;
                int row = f >> 3, cc = f & 7;
                uint32_t so = row * 128 + (((cc ^ row) & 7) << 4);
                long go = (long)row * (K2 * 2);
                CP_ASYNC16(Ad + so, Ab + go + ao  + cc * 16);
                CP_ASYNC16(B0 + so, Bb + go + bo0 + cc * 16);
            }
        }
        CP_COMMIT();
    };

    float acc[2][8][4];
#pragma unroll
    for (int i = 0; i < 2; i++)
#pragma unroll
        for (int j = 0; j < 8; j++)
#pragma unroll
            for (int e = 0; e < 4; e++) acc[i][j][e] = 0.f;

    int xr = lane & 7;
    int aRow0 = m0w + (lane & 15);
    int aU = lane >> 4;
    int bRowB = n0w + (lane & 7) + ((lane >> 4) << 3);
    int bU = (lane >> 3) & 1;

    load_super(0, 0);

    for (int sc = 0; sc < NSUPER; sc++) {
        if (sc + 1 < NSUPER) {
            load_super(sc + 1, (sc + 1) & 1);
            asm volatile("cp.async.wait_group 1;" ::: "memory");
        } else {
            asm volatile("cp.async.wait_group 0;" ::: "memory");
        }
        __syncthreads();

        uint32_t Abase = sbase + (sc & 1) * 49152u;
        uint32_t B0base = Abase + 16384u;
        uint32_t B1base = Abase + 32768u;
        bool dual = (sc < 12);
#pragma unroll
        for (int s = 0; s < 4; s++) {
            uint32_t a[2][4];
#pragma unroll
            for (int i = 0; i < 2; i++) {
                int u = 2 * s + aU;
                uint32_t addr = Abase + (aRow0 + 16 * i) * 128 + ((u ^ xr) << 4);
                ldsm_x4(a[i][0], a[i][1], a[i][2], a[i][3], addr);
            }
            {
                uint32_t b[4][4];
#pragma unroll
                for (int g = 0; g < 4; g++) {
                    int u = 2 * s + bU;
                    uint32_t addr = B0base + (bRowB + 16 * g) * 128 + ((u ^ xr) << 4);
                    ldsm_x4(b[g][0], b[g][1], b[g][2], b[g][3], addr);
                }
#pragma unroll
                for (int i = 0; i < 2; i++)
#pragma unroll
                    for (int g = 0; g < 4; g++) {
                        mma_bf16(acc[i][2 * g],     a[i], b[g][0], b[g][1]);
                        mma_bf16(acc[i][2 * g + 1], a[i], b[g][2], b[g][3]);
                    }
            }
            if (dual) {
                uint32_t b[4][4];
#pragma unroll
                for (int g = 0; g < 4; g++) {
                    int u = 2 * s + bU;
                    uint32_t addr = B1base + (bRowB + 16 * g) * 128 + ((u ^ xr) << 4);
                    ldsm_x4(b[g][0], b[g][1], b[g][2], b[g][3], addr);
                }
#pragma unroll
                for (int i = 0; i < 2; i++)
#pragma unroll
                    for (int g = 0; g < 4; g++) {
                        mma_bf16(acc[i][2 * g],     a[i], b[g][0], b[g][1]);
                        mma_bf16(acc[i][2 * g + 1], a[i], b[g][2], b[g][3]);
                    }
            }
        }
        __syncthreads();
    }

#pragma unroll
    for (int i = 0; i < 2; i++) {
        int rowL = m0 + m0w + 16 * i + (lane >> 2);
#pragma unroll
        for (int j = 0; j < 8; j++) {
            int colL = n0w + 8 * j + 2 * (lane & 3);
            int colG = bx * 128 + colL;
            float2 v0 = make_float2((acc[i][j][0] + bias_s[colL]) * scale,
                                    (acc[i][j][1] + bias_s[colL + 1]) * scale);
            float2 v1 = make_float2((acc[i][j][2] + bias_s[colL]) * scale,
                                    (acc[i][j][3] + bias_s[colL + 1]) * scale);
            *reinterpret_cast<float2*>(&C[(size_t)rowL * E_DIM + colG]) = v0;
            *reinterpret_cast<float2*>(&C[(size_t)(rowL + 8) * E_DIM + colG]) = v1;
        }
    }
}

// ---------------------------------------------------------------------------
// Fused value-GEMM + rule reduction — proven round-13 version (unchanged).
// smem: stage 2x49152 @0 | attn_s @98304 (8704) | bv @107008 (512) |
//       red @107520 (4096) -> 111616
// ---------------------------------------------------------------------------
#define FV_SMEM (111616 + 1024)

__global__ __launch_bounds__(256) void fused_v_mma_kernel(const float* __restrict__ bv) {
    extern __shared__ char smraw[];
    char* sm = (char*)(((uintptr_t)smraw + 1023) & ~(uintptr_t)1023);
    uint32_t sbase = smem_u32(sm);
    float* attn_s = reinterpret_cast<float*>(sm + 98304);
    float* bv_s   = reinterpret_cast<float*>(sm + 107008);
    float* red    = reinterpret_cast<float*>(sm + 107520);

    int tid = threadIdx.x;
    int lane = tid & 31, wid = tid >> 5;
    int wm = wid & 3, wn = wid >> 2;
    int m0w = wm * 32, n0w = wn * 64;
    int bx = blockIdx.x, by = blockIdx.y;
    int m0 = by * 128;
    int h = bx >> 3;
    int dbase = (bx & 7) * 8;

    const char* Ab = (const char*)g_A2 + (size_t)m0 * (K2 * 2);
    const char* Bb = (const char*)g_W2 + (size_t)(bx * 128) * (K2 * 2);

#pragma unroll
    for (int it = 0; it < 8; it++) {
        int f = tid + it * 256;
        int row = f >> 4, r = f & 15;
        attn_s[row * 17 + r] = g_attn[(size_t)(m0 + row) * (HN * RN) + h * RN + r];
    }
    if (tid < 128) bv_s[tid] = bv[bx * 128 + tid];

    auto load_super = [&](int sc, int buf) {
        uint32_t Ad = sbase + buf * 49152u;
        uint32_t B0 = Ad + 16384u;
        uint32_t B1 = Ad + 32768u;
        if (sc < 12) {
            long ao  = (long)sc * 128;
            long bo0 = (long)sc * 128;
            long bo1 = 1536 + (long)sc * 128;
#pragma unroll
            for (int it = 0; it < 4; it++) {
                int f = tid + it * 256;
                int row = f >> 3, cc = f & 7;
                uint32_t so = row * 128 + (((cc ^ row) & 7) << 4);
                long go = (long)row * (K2 * 2);
                CP_ASYNC16(Ad + so, Ab + go + ao  + cc * 16);
                CP_ASYNC16(B0 + so, Bb + go + bo0 + cc * 16);
                CP_ASYNC16(B1 + so, Bb + go + bo1 + cc * 16);
            }
        } else {
            int i = sc - 12;
            long ao  = 1536 + (long)i * 128;
            long bo0 = (long)i * 128;
#pragma unroll
            for (int it = 0; it < 4; it++) {
                int f = tid + it * 256;
                int row = f >> 3, cc = f & 7;
                uint32_t so = row * 128 + (((cc ^ row) & 7) << 4);
                long go = (long)row * (K2 * 2);
                CP_ASYNC16(Ad + so, Ab + go + ao  + cc * 16);
                CP_ASYNC16(B0 + so, Bb + go + bo0 + cc * 16);
            }
        }
        CP_COMMIT();
    };

    float acc[2][8][4];
#pragma unroll
    for (int i = 0; i < 2; i++)
#pragma unroll
        for (int j = 0; j < 8; j++)
#pragma unroll
            for (int e = 0; e < 4; e++) acc[i][j][e] = 0.f;

    int xr = lane & 7;
    int aRow0 = m0w + (lane & 15);
    int aU = lane >> 4;
    int bRowB = n0w + (lane & 7) + ((lane >> 4) << 3);
    int bU = (lane >> 3) & 1;

    load_super(0, 0);

    for (int sc = 0; sc < NSUPER; sc++) {
        if (sc + 1 < NSUPER) {
            load_super(sc + 1, (sc + 1) & 1);
            asm volatile("cp.async.wait_group 1;" ::: "memory");
        } else {
            asm volatile("cp.async.wait_group 0;" ::: "memory");
        }
        __syncthreads();

        uint32_t Abase = sbase + (sc & 1) * 49152u;
        uint32_t B0base = Abase + 16384u;
        uint32_t B1base = Abase + 32768u;
        bool dual = (sc < 12);
#pragma unroll
        for (int s = 0; s < 4; s++) {
            uint32_t a[2][4];
#pragma unroll
            for (int i = 0; i < 2; i++) {
                int u = 2 * s + aU;
                uint32_t addr = Abase + (aRow0 + 16 * i) * 128 + ((u ^ xr) << 4);
                ldsm_x4(a[i][0], a[i][1], a[i][2], a[i][3], addr);
            }
            {
                uint32_t b[4][4];
#pragma unroll
                for (int g = 0; g < 4; g++) {
                    int u = 2 * s + bU;
                    uint32_t addr = B0base + (bRowB + 16 * g) * 128 + ((u ^ xr) << 4);
                    ldsm_x4(b[g][0], b[g][1], b[g][2], b[g][3], addr);
                }
#pragma unroll
                for (int i = 0; i < 2; i++)
#pragma unroll
                    for (int g = 0; g < 4; g++) {
                        mma_bf16(acc[i][2 * g],     a[i], b[g][0], b[g][1]);
                        mma_bf16(acc[i][2 * g + 1], a[i], b[g][2], b[g][3]);
                    }
            }
            if (dual) {
                uint32_t b[4][4];
#pragma unroll
                for (int g = 0; g < 4; g++) {
                    int u = 2 * s + bU;
                    uint32_t addr = B1base + (bRowB + 16 * g) * 128 + ((u ^ xr) << 4);
                    ldsm_x4(b[g][0], b[g][1], b[g][2], b[g][3], addr);
                }
#pragma unroll
                for (int i = 0; i < 2; i++)
#pragma unroll
                    for (int g = 0; g < 4; g++) {
                        mma_bf16(acc[i][2 * g],     a[i], b[g][0], b[g][1]);
                        mma_bf16(acc[i][2 * g + 1], a[i], b[g][2], b[g][3]);
                    }
            }
        }
        __syncthreads();
    }

    // ---- Epilogue: attn-weighted rule reduction ----
    int q = lane & 3, rowg = lane >> 2;
#pragma unroll
    for (int i = 0; i < 2; i++) {
#pragma unroll
        for (int half = 0; half < 2; half++) {
            int rowL = m0w + 16 * i + rowg + 8 * half;
            float p[4] = {0.f, 0.f, 0.f, 0.f};
#pragma unroll
            for (int j = 0; j < 8; j++) {
#pragma unroll
                for (int e = 0; e < 2; e++) {
                    int clw = 8 * j + 2 * q + e;
                    int cl = n0w + clw;
                    float val = (acc[i][j][half * 2 + e] + bv_s[cl]) * 0.125f;
                    p[clw >> 4] = fmaf(attn_s[rowL * 17 + (cl & 15)], val, p[clw >> 4]);
                }
            }
#pragma unroll
            for (int d = 0; d < 4; d++) {
                p[d] += __shfl_xor_sync(0xffffffffu, p[d], 1);
                p[d] += __shfl_xor_sync(0xffffffffu, p[d], 2);
            }
            if (q == 0) {
                red[rowL * 8 + wn * 4 + 0] = p[0];
                red[rowL * 8 + wn * 4 + 1] = p[1];
                red[rowL * 8 + wn * 4 + 2] = p[2];
                red[rowL * 8 + wn * 4 + 3] = p[3];
            }
        }
    }
    __syncthreads();

    // torch scramble scatter + split-bf16 mid -> g_A2x (K2 layout)
    {
        int row = tid >> 1, part = tid & 1;
        float4 v = *reinterpret_cast<float4*>(&red[row * 8 + part * 4]);
        int t = m0 + row;
        int b = t >> 11, s = t & 2047;
        int u = h * 2048 + s;
        int jj = u / 12;
        int col0 = (u - jj * 12) * 64 + dbase + part * 4;
        float vf[4] = {v.x, v.y, v.z, v.w};
        __nv_bfloat16 hv[4], lv[4];
#pragma unroll
        for (int k = 0; k < 4; k++) {
            hv[k] = __float2bfloat16(vf[k]);
            lv[k] = __float2bfloat16(vf[k] - __bfloat162float(hv[k]));
        }
        size_t base = (size_t)(b * 2048 + jj) * K2 + col0;
        *reinterpret_cast<uint2*>(&g_A2x[base])       = *reinterpret_cast<uint2*>(hv);
        *reinterpret_cast<uint2*>(&g_A2x[base + 768]) = *reinterpret_cast<uint2*>(lv);
    }
}

// ---------------------------------------------------------------------------
extern "C" void kernel_launch(void* const* d_in, const int* in_sizes, int n_in,
                              void* d_out, int out_size)
{
    const float* query = (const float*)d_in[0];
    const float* value = (const float*)d_in[2];
    const float* rk    = (const float*)d_in[3];
    const float* rw    = (const float*)d_in[4];
    const float* Wq    = (const float*)d_in[5];
    const float* bq    = (const float*)d_in[6];
    const float* Wv    = (const float*)d_in[7];
    const float* bv    = (const float*)d_in[8];
    const float* Wo    = (const float*)d_in[9];
    const float* bo    = (const float*)d_in[10];
    float* out = (float*)d_out;

    cudaFuncSetAttribute(fused_v_mma_kernel,
                         cudaFuncAttributeMaxDynamicSharedMemorySize, FV_SMEM);
    cudaFuncSetAttribute(mma_gemm_kernel,
                         cudaFuncAttributeMaxDynamicSharedMemorySize, MG_SMEM);

    __nv_bfloat16 *A2, *A2x, *W2, *W2q, *W2o;
    float *qbuf;
    cudaGetSymbolAddress((void**)&A2,  g_A2);
    cudaGetSymbolAddress((void**)&A2x, g_A2x);
    cudaGetSymbolAddress((void**)&W2,  g_W2);
    cudaGetSymbolAddress((void**)&W2q, g_W2q);
    cudaGetSymbolAddress((void**)&W2o, g_W2o);
    cudaGetSymbolAddress((void**)&qbuf, g_q);

    // conversions: query+value in one launch; Wq+Wo in one launch; Wv alone
    convert_A2_kernel<<<2 * (T_TOK * E_DIM) / 256, 256>>>(query, value);
    convert_Wqo_kernel<<<dim3(E_DIM / 32, E_DIM / 32, 2), 256>>>(Wq, Wo);
    convert_W_kernel<<<dim3(ER / 32, E_DIM / 32), 256>>>(Wv, W2, ER);

    // q-projection + fuzzy attn
    mma_gemm_kernel<<<dim3(E_DIM / 128, T_TOK / 128), 256, MG_SMEM>>>(
        A2x, W2q, bq, qbuf, 0.125f);
    attn_kernel<<<dim3(T_TOK / 32, HN), 512>>>(rk, rw);

    // fused value-path GEMM + rule reduction (writes split mid into A2x)
    fused_v_mma_kernel<<<dim3(ER / 128, T_TOK / 128), 256, FV_SMEM>>>(bv);

    // output projection (A2x already split by fused epilogue)
    mma_gemm_kernel<<<dim3(E_DIM / 128, T_TOK / 128), 256, MG_SMEM>>>(
        A2x, W2o, bo, out, 1.0f);
}

// round 17
// speedup vs baseline: 1.2426x; 1.0211x over previous
#include <cuda_runtime.h>
#include <cuda_bf16.h>
#include <cstdint>

#define T_TOK 4096
#define E_DIM 768
#define HN 12
#define RN 16
#define HD 64
#define ER 12288
#define K2 1536          // compact split-bf16 storage: [hi | lo]
#define NSUPER 24        // phased schedule: 12 dual + 12 single superchunks

// ---------------------------------------------------------------------------
// Scratch (__device__ globals; allocation-free rule)
// ---------------------------------------------------------------------------
__device__ float g_q[T_TOK * E_DIM];
__device__ float g_attn[T_TOK * HN * RN];
__device__ __align__(128) __nv_bfloat16 g_A2[(size_t)T_TOK * K2];    // value  [Vh|Vl]
__device__ __align__(128) __nv_bfloat16 g_A2x[(size_t)T_TOK * K2];   // query, then mid (split, scrambled)
__device__ __align__(128) __nv_bfloat16 g_W2[(size_t)ER * K2];       // Wv  [Wh|Wl], [N,K] K-major
__device__ __align__(128) __nv_bfloat16 g_W2q[(size_t)E_DIM * K2];   // Wq
__device__ __align__(128) __nv_bfloat16 g_W2o[(size_t)E_DIM * K2];   // Wo

// ---------------------------------------------------------------------------
__device__ __forceinline__ uint32_t smem_u32(const void* p) {
    uint32_t a;
    asm("{ .reg .u64 t; cvta.to.shared.u64 t, %1; cvt.u32.u64 %0, t; }" : "=r"(a) : "l"(p));
    return a;
}

#define CP_ASYNC16(dst, src) \
    asm volatile("cp.async.cg.shared.global [%0], [%1], 16;" :: "r"(dst), "l"(src))
#define CP_COMMIT() asm volatile("cp.async.commit_group;" ::: "memory")

__device__ __forceinline__ void ldsm_x4(uint32_t& r0, uint32_t& r1, uint32_t& r2,
                                        uint32_t& r3, uint32_t addr) {
    asm volatile("ldmatrix.sync.aligned.m8n8.x4.shared.b16 {%0,%1,%2,%3}, [%4];"
                 : "=r"(r0), "=r"(r1), "=r"(r2), "=r"(r3) : "r"(addr));
}

__device__ __forceinline__ void mma_bf16(float* c, const uint32_t* a,
                                         uint32_t b0, uint32_t b1) {
    asm volatile(
        "mma.sync.aligned.m16n8k16.row.col.f32.bf16.bf16.f32 "
        "{%0,%1,%2,%3}, {%4,%5,%6,%7}, {%8,%9}, {%0,%1,%2,%3};"
        : "+f"(c[0]), "+f"(c[1]), "+f"(c[2]), "+f"(c[3])
        : "r"(a[0]), "r"(a[1]), "r"(a[2]), "r"(a[3]), "r"(b0), "r"(b1));
}

// ---------------------------------------------------------------------------
// Fuzzy membership + 16-wide softmax (proven, unchanged)
// ---------------------------------------------------------------------------
__global__ __launch_bounds__(512) void attn_kernel(
    const float* __restrict__ rk, const float* __restrict__ rw)
{
    __shared__ float rkT[HD * RN];
    __shared__ float iwT[HD * RN];
    __shared__ float q_s[32 * 68];

    int tid = threadIdx.x;
    int t0 = blockIdx.x * 32;
    int h  = blockIdx.y;

#pragma unroll
    for (int it = 0; it < 2; it++) {
        int idx = tid + it * 512;
        int r = idx >> 6, d = idx & 63;
        float k = rk[h * (RN * HD) + idx];
        float w = rw[h * (RN * HD) + idx];
        rkT[d * RN + r] = k;
        iwT[d * RN + r] = 1.0f / (w * w);
    }
    {
        int row = tid >> 4, c = tid & 15;
        float4 v = *reinterpret_cast<const float4*>(
            &g_q[(size_t)(t0 + row) * E_DIM + h * HD + c * 4]);
        *reinterpret_cast<float4*>(&q_s[row * 68 + c * 4]) = v;
    }
    __syncthreads();

    int r  = tid & 15;
    int tl = tid >> 4;

    float s = 0.f;
#pragma unroll
    for (int d = 0; d < HD; d++) {
        float diff = q_s[tl * 68 + d] - rkT[d * RN + r];
        s = fmaf(diff * diff, iwT[d * RN + r], s);
    }
    float z = -0.5f * s * (1.0f / 64.0f);

    float m = z;
#pragma unroll
    for (int o = 8; o; o >>= 1) m = fmaxf(m, __shfl_xor_sync(0xffffffffu, m, o));
    float e = expf(z - m);
    float sum = e;
#pragma unroll
    for (int o = 8; o; o >>= 1) sum += __shfl_xor_sync(0xffffffffu, sum, o);

    g_attn[(size_t)(t0 + tl) * (HN * RN) + h * RN + r] = e / sum;
}

// ---------------------------------------------------------------------------
// Split-bf16 conversions — merged launches (proven round-14 versions)
// ---------------------------------------------------------------------------
__global__ __launch_bounds__(256) void convert_A2_kernel(
    const float* __restrict__ query, const float* __restrict__ value)
{
    const int half = (T_TOK * E_DIM) / 256;
    int bb = blockIdx.x;
    const float* src = (bb < half) ? query : value;
    __nv_bfloat16* dst;
    if (bb < half) { dst = g_A2x; } else { dst = g_A2; bb -= half; }
    int idx = bb * 256 + threadIdx.x;
    int t = idx / E_DIM, e = idx - t * E_DIM;
    float v = src[idx];
    __nv_bfloat16 hi = __float2bfloat16(v);
    __nv_bfloat16 lo = __float2bfloat16(v - __bfloat162float(hi));
    size_t base = (size_t)t * K2 + e;
    dst[base]       = hi;
    dst[base + 768] = lo;
}

__global__ __launch_bounds__(256) void convert_W_kernel(
    const float* __restrict__ W, __nv_bfloat16* __restrict__ dst, int ldW)
{
    __shared__ float s[32][33];
    int c0 = blockIdx.x * 32, e0 = blockIdx.y * 32;
    int tx = threadIdx.x & 31, ty = threadIdx.x >> 5;
#pragma unroll
    for (int it = 0; it < 4; it++) {
        int er = ty + it * 8;
        s[er][tx] = W[(size_t)(e0 + er) * ldW + c0 + tx];
    }
    __syncthreads();
#pragma unroll
    for (int it = 0; it < 4; it++) {
        int cr = ty + it * 8;
        float v = s[tx][cr];
        __nv_bfloat16 hi = __float2bfloat16(v);
        __nv_bfloat16 lo = __float2bfloat16(v - __bfloat162float(hi));
        size_t base = (size_t)(c0 + cr) * K2 + e0 + tx;
        dst[base]       = hi;
        dst[base + 768] = lo;
    }
}

__global__ __launch_bounds__(256) void convert_Wqo_kernel(
    const float* __restrict__ Wq, const float* __restrict__ Wo)
{
    __shared__ float s[32][33];
    const float* W = (blockIdx.z == 0) ? Wq : Wo;
    __nv_bfloat16* dst = (blockIdx.z == 0) ? g_W2q : g_W2o;
    int c0 = blockIdx.x * 32, e0 = blockIdx.y * 32;
    int tx = threadIdx.x & 31, ty = threadIdx.x >> 5;
#pragma unroll
    for (int it = 0; it < 4; it++) {
        int er = ty + it * 8;
        s[er][tx] = W[(size_t)(e0 + er) * E_DIM + c0 + tx];
    }
    __syncthreads();
#pragma unroll
    for (int it = 0; it < 4; it++) {
        int cr = ty + it * 8;
        float v = s[tx][cr];
        __nv_bfloat16 hi = __float2bfloat16(v);
        __nv_bfloat16 lo = __float2bfloat16(v - __bfloat162float(hi));
        size_t base = (size_t)(c0 + cr) * K2 + e0 + tx;
        dst[base]       = hi;
        dst[base + 768] = lo;
    }
}

// ---------------------------------------------------------------------------
// Projection GEMM — retiled 128x64 (grid 12x32 = 384 CTAs), phased schedule.
// 8 warps 4M x 2N, warp tile 32x32. Per-buffer smem: A 16K @+0, B0 8K @+16K,
// B1 8K @+24K (32KB); double-buffered 64KB; bias @65536.
// ---------------------------------------------------------------------------
#define MG_SMEM (65536 + 256 + 1024)

__global__ __launch_bounds__(256) void mma_gemm_kernel(
    const __nv_bfloat16* __restrict__ A2, const __nv_bfloat16* __restrict__ W2,
    const float* __restrict__ bias, float* __restrict__ C, float scale)
{
    extern __shared__ char smraw[];
    char* sm = (char*)(((uintptr_t)smraw + 1023) & ~(uintptr_t)1023);
    uint32_t sbase = smem_u32(sm);
    float* bias_s = reinterpret_cast<float*>(sm + 65536);

    int tid = threadIdx.x;
    int lane = tid & 31, wid = tid >> 5;
    int wm = wid & 3, wn = wid >> 2;
    int m0w = wm * 32, n0w = wn * 32;
    int bx = blockIdx.x, by = blockIdx.y;
    int m0 = by * 128;

    const char* Ab = (const char*)A2 + (size_t)m0 * (K2 * 2);
    const char* Bb = (const char*)W2 + (size_t)(bx * 64) * (K2 * 2);

    if (tid < 64) bias_s[tid] = bias[bx * 64 + tid];

    auto load_super = [&](int sc, int buf) {
        uint32_t Ad = sbase + buf * 32768u;
        uint32_t B0 = Ad + 16384u;
        uint32_t B1 = Ad + 24576u;
        if (sc < 12) {
            long ao  = (long)sc * 128;
            long bo0 = (long)sc * 128;
            long bo1 = 1536 + (long)sc * 128;
#pragma unroll
            for (int it = 0; it < 4; it++) {          // A: 128 rows
                int f = tid + it * 256;
                int row = f >> 3, cc = f & 7;
                uint32_t so = row * 128 + (((cc ^ row) & 7) << 4);
                CP_ASYNC16(Ad + so, Ab + (long)row * (K2 * 2) + ao + cc * 16);
            }
#pragma unroll
            for (int it = 0; it < 2; it++) {          // B0+B1: 64 rows each
                int f = tid + it * 256;
                int row = f >> 3, cc = f & 7;
                uint32_t so = row * 128 + (((cc ^ row) & 7) << 4);
                long go = (long)row * (K2 * 2);
                CP_ASYNC16(B0 + so, Bb + go + bo0 + cc * 16);
                CP_ASYNC16(B1 + so, Bb + go + bo1 + cc * 16);
            }
        } else {
            int i = sc - 12;
            long ao  = 1536 + (long)i * 128;
            long bo0 = (long)i * 128;
#pragma unroll
            for (int it = 0; it < 4; it++) {
                int f = tid + it * 256;
                int row = f >> 3, cc = f & 7;
                uint32_t so = row * 128 + (((cc ^ row) & 7) << 4);
                CP_ASYNC16(Ad + so, Ab + (long)row * (K2 * 2) + ao + cc * 16);
            }
#pragma unroll
            for (int it = 0; it < 2; it++) {
                int f = tid + it * 256;
                int row = f >> 3, cc = f & 7;
                uint32_t so = row * 128 + (((cc ^ row) & 7) << 4);
                CP_ASYNC16(B0 + so, Bb + (long)row * (K2 * 2) + bo0 + cc * 16);
            }
        }
        CP_COMMIT();
    };

    float acc[2][4][4];
#pragma unroll
    for (int i = 0; i < 2; i++)
#pragma unroll
        for (int j = 0; j < 4; j++)
#pragma unroll
            for (int e = 0; e < 4; e++) acc[i][j][e] = 0.f;

    int xr = lane & 7;
    int aRow0 = m0w + (lane & 15);
    int aU = lane >> 4;
    int bRowB = n0w + (lane & 7) + ((lane >> 4) << 3);
    int bU = (lane >> 3) & 1;

    load_super(0, 0);

    for (int sc = 0; sc < NSUPER; sc++) {
        if (sc + 1 < NSUPER) {
            load_super(sc + 1, (sc + 1) & 1);
            asm volatile("cp.async.wait_group 1;" ::: "memory");
        } else {
            asm volatile("cp.async.wait_group 0;" ::: "memory");
        }
        __syncthreads();

        uint32_t Abase = sbase + (sc & 1) * 32768u;
        uint32_t B0base = Abase + 16384u;
        uint32_t B1base = Abase + 24576u;
        bool dual = (sc < 12);
#pragma unroll
        for (int s = 0; s < 4; s++) {
            uint32_t a[2][4];
#pragma unroll
            for (int i = 0; i < 2; i++) {
                int u = 2 * s + aU;
                uint32_t addr = Abase + (aRow0 + 16 * i) * 128 + ((u ^ xr) << 4);
                ldsm_x4(a[i][0], a[i][1], a[i][2], a[i][3], addr);
            }
            {
                uint32_t b[2][4];
#pragma unroll
                for (int g = 0; g < 2; g++) {
                    int u = 2 * s + bU;
                    uint32_t addr = B0base + (bRowB + 16 * g) * 128 + ((u ^ xr) << 4);
                    ldsm_x4(b[g][0], b[g][1], b[g][2], b[g][3], addr);
                }
#pragma unroll
                for (int i = 0; i < 2; i++)
#pragma unroll
                    for (int g = 0; g < 2; g++) {
                        mma_bf16(acc[i][2 * g],     a[i], b[g][0], b[g][1]);
                        mma_bf16(acc[i][2 * g + 1], a[i], b[g][2], b[g][3]);
                    }
            }
            if (dual) {
                uint32_t b[2][4];
#pragma unroll
                for (int g = 0; g < 2; g++) {
                    int u = 2 * s + bU;
                    uint32_t addr = B1base + (bRowB + 16 * g) * 128 + ((u ^ xr) << 4);
                    ldsm_x4(b[g][0], b[g][1], b[g][2], b[g][3], addr);
                }
#pragma unroll
                for (int i = 0; i < 2; i++)
#pragma unroll
                    for (int g = 0; g < 2; g++) {
                        mma_bf16(acc[i][2 * g],     a[i], b[g][0], b[g][1]);
                        mma_bf16(acc[i][2 * g + 1], a[i], b[g][2], b[g][3]);
                    }
            }
        }
        __syncthreads();
    }

#pragma unroll
    for (int i = 0; i < 2; i++) {
        int rowL = m0 + m0w + 16 * i + (lane >> 2);
#pragma unroll
        for (int j = 0; j < 4; j++) {
            int colL = n0w + 8 * j + 2 * (lane & 3);
            int colG = bx * 64 + colL;
            float2 v0 = make_float2((acc[i][j][0] + bias_s[colL]) * scale,
                                    (acc[i][j][1] + bias_s[colL + 1]) * scale);
            float2 v1 = make_float2((acc[i][j][2] + bias_s[colL]) * scale,
                                    (acc[i][j][3] + bias_s[colL + 1]) * scale);
            *reinterpret_cast<float2*>(&C[(size_t)rowL * E_DIM + colG]) = v0;
            *reinterpret_cast<float2*>(&C[(size_t)(rowL + 8) * E_DIM + colG]) = v1;
        }
    }
}

// ---------------------------------------------------------------------------
// Fused value-GEMM + rule reduction — proven round-13 version (unchanged).
// smem: stage 2x49152 @0 | attn_s @98304 (8704) | bv @107008 (512) |
//       red @107520 (4096) -> 111616
// ---------------------------------------------------------------------------
#define FV_SMEM (111616 + 1024)

__global__ __launch_bounds__(256) void fused_v_mma_kernel(const float* __restrict__ bv) {
    extern __shared__ char smraw[];
    char* sm = (char*)(((uintptr_t)smraw + 1023) & ~(uintptr_t)1023);
    uint32_t sbase = smem_u32(sm);
    float* attn_s = reinterpret_cast<float*>(sm + 98304);
    float* bv_s   = reinterpret_cast<float*>(sm + 107008);
    float* red    = reinterpret_cast<float*>(sm + 107520);

    int tid = threadIdx.x;
    int lane = tid & 31, wid = tid >> 5;
    int wm = wid & 3, wn = wid >> 2;
    int m0w = wm * 32, n0w = wn * 64;
    int bx = blockIdx.x, by = blockIdx.y;
    int m0 = by * 128;
    int h = bx >> 3;
    int dbase = (bx & 7) * 8;

    const char* Ab = (const char*)g_A2 + (size_t)m0 * (K2 * 2);
    const char* Bb = (const char*)g_W2 + (size_t)(bx * 128) * (K2 * 2);

#pragma unroll
    for (int it = 0; it < 8; it++) {
        int f = tid + it * 256;
        int row = f >> 4, r = f & 15;
        attn_s[row * 17 + r] = g_attn[(size_t)(m0 + row) * (HN * RN) + h * RN + r];
    }
    if (tid < 128) bv_s[tid] = bv[bx * 128 + tid];

    auto load_super = [&](int sc, int buf) {
        uint32_t Ad = sbase + buf * 49152u;
        uint32_t B0 = Ad + 16384u;
        uint32_t B1 = Ad + 32768u;
        if (sc < 12) {
            long ao  = (long)sc * 128;
            long bo0 = (long)sc * 128;
            long bo1 = 1536 + (long)sc * 128;
#pragma unroll
            for (int it = 0; it < 4; it++) {
                int f = tid + it * 256;
                int row = f >> 3, cc = f & 7;
                uint32_t so = row * 128 + (((cc ^ row) & 7) << 4);
                long go = (long)row * (K2 * 2);
                CP_ASYNC16(Ad + so, Ab + go + ao  + cc * 16);
                CP_ASYNC16(B0 + so, Bb + go + bo0 + cc * 16);
                CP_ASYNC16(B1 + so, Bb + go + bo1 + cc * 16);
            }
        } else {
            int i = sc - 12;
            long ao  = 1536 + (long)i * 128;
            long bo0 = (long)i * 128;
#pragma unroll
            for (int it = 0; it < 4; it++) {
                int f = tid + it * 256;
                int row = f >> 3, cc = f & 7;
                uint32_t so = row * 128 + (((cc ^ row) & 7) << 4);
                long go = (long)row * (K2 * 2);
                CP_ASYNC16(Ad + so, Ab + go + ao  + cc * 16);
                CP_ASYNC16(B0 + so, Bb + go + bo0 + cc * 16);
            }
        }
        CP_COMMIT();
    };

    float acc[2][8][4];
#pragma unroll
    for (int i = 0; i < 2; i++)
#pragma unroll
        for (int j = 0; j < 8; j++)
#pragma unroll
            for (int e = 0; e < 4; e++) acc[i][j][e] = 0.f;

    int xr = lane & 7;
    int aRow0 = m0w + (lane & 15);
    int aU = lane >> 4;
    int bRowB = n0w + (lane & 7) + ((lane >> 4) << 3);
    int bU = (lane >> 3) & 1;

    load_super(0, 0);

    for (int sc = 0; sc < NSUPER; sc++) {
        if (sc + 1 < NSUPER) {
            load_super(sc + 1, (sc + 1) & 1);
            asm volatile("cp.async.wait_group 1;" ::: "memory");
        } else {
            asm volatile("cp.async.wait_group 0;" ::: "memory");
        }
        __syncthreads();

        uint32_t Abase = sbase + (sc & 1) * 49152u;
        uint32_t B0base = Abase + 16384u;
        uint32_t B1base = Abase + 32768u;
        bool dual = (sc < 12);
#pragma unroll
        for (int s = 0; s < 4; s++) {
            uint32_t a[2][4];
#pragma unroll
            for (int i = 0; i < 2; i++) {
                int u = 2 * s + aU;
                uint32_t addr = Abase + (aRow0 + 16 * i) * 128 + ((u ^ xr) << 4);
                ldsm_x4(a[i][0], a[i][1], a[i][2], a[i][3], addr);
            }
            {
                uint32_t b[4][4];
#pragma unroll
                for (int g = 0; g < 4; g++) {
                    int u = 2 * s + bU;
                    uint32_t addr = B0base + (bRowB + 16 * g) * 128 + ((u ^ xr) << 4);
                    ldsm_x4(b[g][0], b[g][1], b[g][2], b[g][3], addr);
                }
#pragma unroll
                for (int i = 0; i < 2; i++)
#pragma unroll
                    for (int g = 0; g < 4; g++) {
                        mma_bf16(acc[i][2 * g],     a[i], b[g][0], b[g][1]);
                        mma_bf16(acc[i][2 * g + 1], a[i], b[g][2], b[g][3]);
                    }
            }
            if (dual) {
                uint32_t b[4][4];
#pragma unroll
                for (int g = 0; g < 4; g++) {
                    int u = 2 * s + bU;
                    uint32_t addr = B1base + (bRowB + 16 * g) * 128 + ((u ^ xr) << 4);
                    ldsm_x4(b[g][0], b[g][1], b[g][2], b[g][3], addr);
                }
#pragma unroll
                for (int i = 0; i < 2; i++)
#pragma unroll
                    for (int g = 0; g < 4; g++) {
                        mma_bf16(acc[i][2 * g],     a[i], b[g][0], b[g][1]);
                        mma_bf16(acc[i][2 * g + 1], a[i], b[g][2], b[g][3]);
                    }
            }
        }
        __syncthreads();
    }

    // ---- Epilogue: attn-weighted rule reduction ----
    int q = lane & 3, rowg = lane >> 2;
#pragma unroll
    for (int i = 0; i < 2; i++) {
#pragma unroll
        for (int half = 0; half < 2; half++) {
            int rowL = m0w + 16 * i + rowg + 8 * half;
            float p[4] = {0.f, 0.f, 0.f, 0.f};
#pragma unroll
            for (int j = 0; j < 8; j++) {
#pragma unroll
                for (int e = 0; e < 2; e++) {
                    int clw = 8 * j + 2 * q + e;
                    int cl = n0w + clw;
                    float val = (acc[i][j][half * 2 + e] + bv_s[cl]) * 0.125f;
                    p[clw >> 4] = fmaf(attn_s[rowL * 17 + (cl & 15)], val, p[clw >> 4]);
                }
            }
#pragma unroll
            for (int d = 0; d < 4; d++) {
                p[d] += __shfl_xor_sync(0xffffffffu, p[d], 1);
                p[d] += __shfl_xor_sync(0xffffffffu, p[d], 2);
            }
            if (q == 0) {
                red[rowL * 8 + wn * 4 + 0] = p[0];
                red[rowL * 8 + wn * 4 + 1] = p[1];
                red[rowL * 8 + wn * 4 + 2] = p[2];
                red[rowL * 8 + wn * 4 + 3] = p[3];
            }
        }
    }
    __syncthreads();

    // torch scramble scatter + split-bf16 mid -> g_A2x (K2 layout)
    {
        int row = tid >> 1, part = tid & 1;
        float4 v = *reinterpret_cast<float4*>(&red[row * 8 + part * 4]);
        int t = m0 + row;
        int b = t >> 11, s = t & 2047;
        int u = h * 2048 + s;
        int jj = u / 12;
        int col0 = (u - jj * 12) * 64 + dbase + part * 4;
        float vf[4] = {v.x, v.y, v.z, v.w};
        __nv_bfloat16 hv[4], lv[4];
#pragma unroll
        for (int k = 0; k < 4; k++) {
            hv[k] = __float2bfloat16(vf[k]);
            lv[k] = __float2bfloat16(vf[k] - __bfloat162float(hv[k]));
        }
        size_t base = (size_t)(b * 2048 + jj) * K2 + col0;
        *reinterpret_cast<uint2*>(&g_A2x[base])       = *reinterpret_cast<uint2*>(hv);
        *reinterpret_cast<uint2*>(&g_A2x[base + 768]) = *reinterpret_cast<uint2*>(lv);
    }
}

// ---------------------------------------------------------------------------
extern "C" void kernel_launch(void* const* d_in, const int* in_sizes, int n_in,
                              void* d_out, int out_size)
{
    const float* query = (const float*)d_in[0];
    const float* value = (const float*)d_in[2];
    const float* rk    = (const float*)d_in[3];
    const float* rw    = (const float*)d_in[4];
    const float* Wq    = (const float*)d_in[5];
    const float* bq    = (const float*)d_in[6];
    const float* Wv    = (const float*)d_in[7];
    const float* bv    = (const float*)d_in[8];
    const float* Wo    = (const float*)d_in[9];
    const float* bo    = (const float*)d_in[10];
    float* out = (float*)d_out;

    cudaFuncSetAttribute(fused_v_mma_kernel,
                         cudaFuncAttributeMaxDynamicSharedMemorySize, FV_SMEM);
    cudaFuncSetAttribute(mma_gemm_kernel,
                         cudaFuncAttributeMaxDynamicSharedMemorySize, MG_SMEM);

    __nv_bfloat16 *A2, *A2x, *W2, *W2q, *W2o;
    float *qbuf;
    cudaGetSymbolAddress((void**)&A2,  g_A2);
    cudaGetSymbolAddress((void**)&A2x, g_A2x);
    cudaGetSymbolAddress((void**)&W2,  g_W2);
    cudaGetSymbolAddress((void**)&W2q, g_W2q);
    cudaGetSymbolAddress((void**)&W2o, g_W2o);
    cudaGetSymbolAddress((void**)&qbuf, g_q);

    // conversions: query+value in one launch; Wq+Wo in one launch; Wv alone
    convert_A2_kernel<<<2 * (T_TOK * E_DIM) / 256, 256>>>(query, value);
    convert_Wqo_kernel<<<dim3(E_DIM / 32, E_DIM / 32, 2), 256>>>(Wq, Wo);
    convert_W_kernel<<<dim3(ER / 32, E_DIM / 32), 256>>>(Wv, W2, ER);

    // q-projection + fuzzy attn
    mma_gemm_kernel<<<dim3(E_DIM / 64, T_TOK / 128), 256, MG_SMEM>>>(
        A2x, W2q, bq, qbuf, 0.125f);
    attn_kernel<<<dim3(T_TOK / 32, HN), 512>>>(rk, rw);

    // fused value-path GEMM + rule reduction (writes split mid into A2x)
    fused_v_mma_kernel<<<dim3(ER / 128, T_TOK / 128), 256, FV_SMEM>>>(bv);

    // output projection (A2x already split by fused epilogue)
    mma_gemm_kernel<<<dim3(E_DIM / 64, T_TOK / 128), 256, MG_SMEM>>>(
        A2x, W2o, bo, out, 1.0f);
}